// round 14
// baseline (speedup 1.0000x reference)
#include <cuda_runtime.h>
#include <cuda_fp16.h>
#include <stdint.h>
#include <math.h>

#define NN   100000
#define EE   800000
#define DDIM 128
#define NBLK 782      // 782*128 = 100096 rows
#define SBLK 391      // scan blocks: 391*256 >= NN

// ---------------- scratch (device globals; no runtime alloc) ----------------
__device__ __align__(256) __half g_bufA[(size_t)NBLK * 128 * DDIM];
__device__ __align__(256) __half g_bufB[(size_t)NBLK * 128 * DDIM];
__device__ int   g_deg[NN];
__device__ int   g_rowptr[NN + 1];
__device__ int   g_cursor[NN];
__device__ float g_deginv[NN];
__device__ int   g_colidx[EE];
__device__ int   g_part[512];
__device__ int   g_is64;
// fragment-packed fp16 weights (hi only), kstep-paired warp-contiguous:
// uint4 idx = ((n8*(KCH/2) + kp)*8 + g)*4 + tig ; uint4 = {ksf_even h0, h1, ksf_odd h0, h1}
__device__ __align__(16) unsigned g_Wp[DDIM * 8 * 8];         // proj  KCH=8
__device__ __align__(16) unsigned g_Wb[3][DDIM * 16 * 8];     // layers KCH=16

// ---------------- init + prefix dtype detect ----------------
__global__ void k_init(const unsigned* __restrict__ w) {
    int i = blockIdx.x * blockDim.x + threadIdx.x;
    if (i < NN) g_deg[i] = 0;
    if (blockIdx.x == 0) {
        if (threadIdx.x == 0) g_is64 = 1;
        __syncthreads();
        unsigned acc = 0;
#pragma unroll
        for (int k = 0; k < 16; k++)
            acc |= w[2 * (threadIdx.x + k * 256) + 1];
        if (acc != 0) g_is64 = 0;
    }
}
__device__ __forceinline__ int load_idx(const void* ei, int pos, int is64) {
    if (is64) return (int)((const long long*)ei)[pos];
    return ((const int*)ei)[pos];
}
__global__ void k_hist(const void* __restrict__ ei) {
    int e = blockIdx.x * blockDim.x + threadIdx.x;
    if (e < EE) {
        int d = load_idx(ei, EE + e, g_is64);
        if ((unsigned)d < NN) atomicAdd(&g_deg[d], 1);
    }
}

// ---------------- parallel 3-phase exclusive scan ----------------
__global__ void k_scan1() {
    __shared__ int sh[256];
    int t = threadIdx.x;
    int i = blockIdx.x * 256 + t;
    sh[t] = (i < NN) ? g_deg[i] : 0;
    __syncthreads();
#pragma unroll
    for (int off = 128; off > 0; off >>= 1) {
        if (t < off) sh[t] += sh[t + off];
        __syncthreads();
    }
    if (t == 0) g_part[blockIdx.x] = sh[0];
}
__global__ void k_scan2() {
    __shared__ int sh[512];
    int t = threadIdx.x;
    int v = (t < SBLK) ? g_part[t] : 0;
    sh[t] = v;
    __syncthreads();
#pragma unroll
    for (int off = 1; off < 512; off <<= 1) {
        int u = (t >= off) ? sh[t - off] : 0;
        __syncthreads();
        sh[t] += u;
        __syncthreads();
    }
    if (t < SBLK) g_part[t] = sh[t] - v;
    if (t == SBLK - 1) g_rowptr[NN] = sh[t];
}
__global__ void k_scan3() {
    __shared__ int sh[256];
    int t = threadIdx.x;
    int i = blockIdx.x * 256 + t;
    int d = (i < NN) ? g_deg[i] : 0;
    sh[t] = d;
    __syncthreads();
#pragma unroll
    for (int off = 1; off < 256; off <<= 1) {
        int u = (t >= off) ? sh[t - off] : 0;
        __syncthreads();
        sh[t] += u;
        __syncthreads();
    }
    if (i < NN) {
        int excl = sh[t] - d + g_part[blockIdx.x];
        g_rowptr[i] = excl;
        g_cursor[i] = excl;
        g_deginv[i] = (d > 0) ? 1.0f / (float)d : 0.0f;
    }
}
__global__ void k_fill(const void* __restrict__ ei) {
    int e = blockIdx.x * blockDim.x + threadIdx.x;
    if (e < EE) {
        int is64 = g_is64;
        int s = load_idx(ei, e, is64);
        int d = load_idx(ei, EE + e, is64);
        if ((unsigned)d < NN && (unsigned)s < NN) {
            int p = atomicAdd(&g_cursor[d], 1);
            g_colidx[p] = s;
        }
    }
}

// ---------------- weight conversion: fp32 -> kstep-paired fp16 fragments ----------------
struct ConvArgs {
    const float*  src[7];
    unsigned*     dst[7];
    int           koff[7];
    int           kfull[7];
};
__global__ void k_convert_all(ConvArgs a) {
    int m = blockIdx.y;
    int idx = blockIdx.x * blockDim.x + threadIdx.x;
    if (idx >= DDIM * DDIM) return;
    int n = idx >> 7, k = idx & 127;
    __half h = __float2half_rn(a.src[m][idx]);
    int kg   = a.koff[m] + k;
    int ksf  = kg >> 4;
    int kp   = ksf >> 1;
    int ko   = ksf & 1;
    int kpos = kg & 15;
    int tig  = (kpos >> 1) & 3;
    int hf   = (kpos >> 3) & 1;
    int b    = kpos & 1;
    unsigned u4 = (((unsigned)((n >> 3) * (a.kfull[m] >> 5) + kp) * 8 + (n & 7)) * 4 + tig);
    ((__half*)a.dst[m])[(u4 * 4 + ko * 2 + hf) * 2 + b] = h;
}

// ---------------- common GEMM pieces ----------------
__device__ __forceinline__ unsigned cvt2(float x, float y) {
    __half2 t = __floats2half2_rn(x, y);
    return *reinterpret_cast<unsigned*>(&t);
}
__device__ __forceinline__ void mma_f16(float (&c)[4], const unsigned (&a)[4],
                                        unsigned b0, unsigned b1) {
    asm volatile(
        "mma.sync.aligned.m16n8k16.row.col.f32.f16.f16.f32 "
        "{%0,%1,%2,%3}, {%4,%5,%6,%7}, {%8,%9}, {%0,%1,%2,%3};\n"
        : "+f"(c[0]), "+f"(c[1]), "+f"(c[2]), "+f"(c[3])
        : "r"(a[0]), "r"(a[1]), "r"(a[2]), "r"(a[3]), "r"(b0), "r"(b1));
}
// A smem: 128 rows x (KH*128) k fp16, word stride AWW = KH*64 + 8 (stride ≡ 8 mod 32)
// in-chunk (16 k) word order: word = 2*tig + half (lane reads (k, k+8) halves as one LDS.64)
// word(row, k) = row*AWW + (k>>4)*8 + 2*((k>>1)&3) + ((k>>3)&1)

// ---------------- proj GEMM (KH=1, fp32 A in, fp16 out) ----------------
__global__ void __launch_bounds__(512, 2) k_gemm_proj(
    const float* __restrict__ A0, const unsigned* __restrict__ Bfrag,
    __half* __restrict__ out)
{
    constexpr int KCH = 8;
    constexpr int AWW = 72;
    extern __shared__ unsigned smA[];
    const int tid = threadIdx.x;
    const int w = tid >> 5;
    const int lane = tid & 31;
    const int g = lane >> 2;
    const int tig = lane & 3;
    const int rowgrp = w & 3;
    const int colq = w >> 2;
    const int rowbase = blockIdx.x * 128 + rowgrp * 32;
    int rr[4] = { rowbase + g, rowbase + g + 8, rowbase + g + 16, rowbase + g + 24 };
    bool pp[4];
#pragma unroll
    for (int i = 0; i < 4; i++) pp[i] = rr[i] < NN;

    const uint4* Bf = (const uint4*)Bfrag;
    const int bbase0 = (colq * 4 * (KCH / 2)) * 32 + g * 4 + tig;

    // stage A: coalesced lane-contiguous loads, scatter-store permuted words
#pragma unroll
    for (int it = 0; it < 8; it++) {
        int idx = it * 512 + tid;
        int row = idx >> 5, l = idx & 31;
        int grow = blockIdx.x * 128 + row;
        float4 fv = make_float4(0.f, 0.f, 0.f, 0.f);
        if (grow < NN) fv = *(const float4*)(A0 + (size_t)grow * DDIM + l * 4);
        unsigned sx = cvt2(fv.x, fv.y);
        unsigned sy = cvt2(fv.z, fv.w);
        int m = l & 3;
        int w0 = ((m & 1) << 2) | (m >> 1);
        unsigned* dst = &smA[row * AWW + (l >> 2) * 8];
        dst[w0]     = sx;
        dst[w0 + 2] = sy;
    }
    __syncthreads();

    const unsigned* ar = smA + (rowgrp * 32 + g) * AWW + tig * 2;
    float acc[4][2][4];
#pragma unroll
    for (int t = 0; t < 4; t++)
#pragma unroll
        for (int s = 0; s < 2; s++)
#pragma unroll
            for (int i = 0; i < 4; i++) acc[t][s][i] = 0.f;

#pragma unroll
    for (int kp = 0; kp < KCH / 2; kp++) {
        uint4 bb[4];
#pragma unroll
        for (int t = 0; t < 4; t++)
            bb[t] = Bf[bbase0 + (t * (KCH / 2) + kp) * 32];
#pragma unroll
        for (int sub = 0; sub < 2; sub++) {
            const int ksf = kp * 2 + sub;
            uint2 u00 = *(const uint2*)(ar + ksf * 8);
            uint2 u01 = *(const uint2*)(ar + 8 * AWW + ksf * 8);
            uint2 u10 = *(const uint2*)(ar + 16 * AWW + ksf * 8);
            uint2 u11 = *(const uint2*)(ar + 24 * AWW + ksf * 8);
            unsigned aH[2][4];
            aH[0][0] = u00.x; aH[0][2] = u00.y;
            aH[0][1] = u01.x; aH[0][3] = u01.y;
            aH[1][0] = u10.x; aH[1][2] = u10.y;
            aH[1][1] = u11.x; aH[1][3] = u11.y;
#pragma unroll
            for (int t = 0; t < 4; t++) {
                unsigned b0 = sub ? bb[t].z : bb[t].x;
                unsigned b1 = sub ? bb[t].w : bb[t].y;
                mma_f16(acc[t][0], aH[0], b0, b1);
                mma_f16(acc[t][1], aH[1], b0, b1);
            }
        }
    }
#pragma unroll
    for (int t = 0; t < 4; t++) {
        const int c = colq * 32 + t * 8 + tig * 2;
#pragma unroll
        for (int s = 0; s < 2; s++) {
            if (pp[2*s])
                *(unsigned*)(out + (size_t)rr[2*s] * DDIM + c) = cvt2(acc[t][s][0], acc[t][s][1]);
            if (pp[2*s+1])
                *(unsigned*)(out + (size_t)rr[2*s+1] * DDIM + c) = cvt2(acc[t][s][2], acc[t][s][3]);
        }
    }
}

// ---------------- fused layer GEMM: gather-mean + [mean|h] @ W^T + epilogue ----------------
// EPI: 1 = relu(acc+bias)+identity, 2 = bias + L2-norm -> fp32
// IDIN: 0 = identity fp32 global, 2 = identity = h (smem A1 panel)
template<int EPI, int IDIN>
__global__ void __launch_bounds__(512, 2) k_gemm_agg(
    const __half* __restrict__ H, const unsigned* __restrict__ Bfrag,
    const float* __restrict__ bias, const float* __restrict__ identityf,
    void* __restrict__ outv)
{
    constexpr int KCH = 16;
    constexpr int AWW = 136;
    extern __shared__ unsigned smA[];
    __shared__ float s_red[4][4][32];

    const int tid = threadIdx.x;
    const int w = tid >> 5;
    const int lane = tid & 31;
    const int g = lane >> 2;
    const int tig = lane & 3;
    const int rowgrp = w & 3;
    const int colq = w >> 2;
    const int rowbase = blockIdx.x * 128 + rowgrp * 32;
    int rr[4] = { rowbase + g, rowbase + g + 8, rowbase + g + 16, rowbase + g + 24 };
    bool pp[4];
#pragma unroll
    for (int i = 0; i < 4; i++) pp[i] = rr[i] < NN;

    const uint4* Bf = (const uint4*)Bfrag;
    const int bbase0 = (colq * 4 * (KCH / 2)) * 32 + g * 4 + tig;

    // ---- A1: own h rows (k 128..255), coalesced uint4 loads, permuted STS.32 ----
    // thread covers halves k=8l..8l+7 -> words (2i + (l&1)) of chunk (l>>1), i=0..3
#pragma unroll
    for (int it = 0; it < 4; it++) {
        int idx = it * 512 + tid;
        int row = idx >> 4, l = idx & 15;
        int grow = blockIdx.x * 128 + row;
        uint4 v = make_uint4(0u, 0u, 0u, 0u);
        if (grow < NN) v = *(const uint4*)(H + (size_t)grow * DDIM + l * 8);
        unsigned* dst = &smA[row * AWW + 64 + (l >> 1) * 8 + (l & 1)];
        dst[0] = v.x;
        dst[2] = v.y;
        dst[4] = v.z;
        dst[6] = v.w;
    }

    // ---- A0: gather-mean, warp w handles 8 nodes, MLP=8 ----
#pragma unroll 1
    for (int i = 0; i < 8; i++) {
        int lr = w * 8 + i;
        int node = blockIdx.x * 128 + lr;
        float4 a0 = make_float4(0.f, 0.f, 0.f, 0.f);
        float4 a1 = make_float4(0.f, 0.f, 0.f, 0.f);
        float4 a2 = make_float4(0.f, 0.f, 0.f, 0.f);
        float4 a3 = make_float4(0.f, 0.f, 0.f, 0.f);
        float sc = 0.f;
        if (node < NN) {
            int s = g_rowptr[node], e = g_rowptr[node + 1];
            sc = g_deginv[node];
            int j = s;
            for (; j + 8 <= e; j += 8) {
                uint2 v[8];
#pragma unroll
                for (int k = 0; k < 8; k++)
                    v[k] = *(const uint2*)(H + (size_t)g_colidx[j + k] * DDIM + lane * 4);
#pragma unroll
                for (int k = 0; k < 8; k++) {
                    float2 p0 = __half22float2(*(__half2*)&v[k].x);
                    float2 p1 = __half22float2(*(__half2*)&v[k].y);
                    float4* a = (k & 3) == 0 ? &a0 : (k & 3) == 1 ? &a1 : (k & 3) == 2 ? &a2 : &a3;
                    a->x += p0.x; a->y += p0.y; a->z += p1.x; a->w += p1.y;
                }
            }
            if (j + 4 <= e) {
                uint2 v[4];
#pragma unroll
                for (int k = 0; k < 4; k++)
                    v[k] = *(const uint2*)(H + (size_t)g_colidx[j + k] * DDIM + lane * 4);
#pragma unroll
                for (int k = 0; k < 4; k++) {
                    float2 p0 = __half22float2(*(__half2*)&v[k].x);
                    float2 p1 = __half22float2(*(__half2*)&v[k].y);
                    float4* a = k == 0 ? &a0 : k == 1 ? &a1 : k == 2 ? &a2 : &a3;
                    a->x += p0.x; a->y += p0.y; a->z += p1.x; a->w += p1.y;
                }
                j += 4;
            }
            for (; j < e; j++) {
                uint2 v0 = *(const uint2*)(H + (size_t)g_colidx[j] * DDIM + lane * 4);
                float2 p0 = __half22float2(*(__half2*)&v0.x);
                float2 p1 = __half22float2(*(__half2*)&v0.y);
                a0.x += p0.x; a0.y += p0.y; a0.z += p1.x; a0.w += p1.y;
            }
        }
        // lane covers k=4*lane..4*lane+3: words w0, w0+2 in chunk (lane>>2)
        unsigned sx = cvt2((a0.x + a1.x + a2.x + a3.x) * sc, (a0.y + a1.y + a2.y + a3.y) * sc);
        unsigned sy = cvt2((a0.z + a1.z + a2.z + a3.z) * sc, (a0.w + a1.w + a2.w + a3.w) * sc);
        int m = lane & 3;
        int w0 = ((m & 1) << 2) | (m >> 1);
        unsigned* dst = &smA[lr * AWW + (lane >> 2) * 8];
        dst[w0]     = sx;
        dst[w0 + 2] = sy;
    }
    __syncthreads();

    const unsigned* ar = smA + (rowgrp * 32 + g) * AWW + tig * 2;
    float acc[4][2][4];
#pragma unroll
    for (int t = 0; t < 4; t++)
#pragma unroll
        for (int s = 0; s < 2; s++)
#pragma unroll
            for (int i = 0; i < 4; i++) acc[t][s][i] = 0.f;

#pragma unroll
    for (int kp = 0; kp < KCH / 2; kp++) {
        uint4 bb[4];
#pragma unroll
        for (int t = 0; t < 4; t++)
            bb[t] = Bf[bbase0 + (t * (KCH / 2) + kp) * 32];
#pragma unroll
        for (int sub = 0; sub < 2; sub++) {
            const int ksf = kp * 2 + sub;
            uint2 u00 = *(const uint2*)(ar + ksf * 8);
            uint2 u01 = *(const uint2*)(ar + 8 * AWW + ksf * 8);
            uint2 u10 = *(const uint2*)(ar + 16 * AWW + ksf * 8);
            uint2 u11 = *(const uint2*)(ar + 24 * AWW + ksf * 8);
            unsigned aH[2][4];
            aH[0][0] = u00.x; aH[0][2] = u00.y;
            aH[0][1] = u01.x; aH[0][3] = u01.y;
            aH[1][0] = u10.x; aH[1][2] = u10.y;
            aH[1][1] = u11.x; aH[1][3] = u11.y;
#pragma unroll
            for (int t = 0; t < 4; t++) {
                unsigned b0 = sub ? bb[t].z : bb[t].x;
                unsigned b1 = sub ? bb[t].w : bb[t].y;
                mma_f16(acc[t][0], aH[0], b0, b1);
                mma_f16(acc[t][1], aH[1], b0, b1);
            }
        }
    }

    if (EPI == 1) {
        __half* out = (__half*)outv;
#pragma unroll
        for (int t = 0; t < 4; t++) {
            const int c = colq * 32 + t * 8 + tig * 2;
            float2 bb = *(const float2*)(bias + c);
#pragma unroll
            for (int s2 = 0; s2 < 4; s2++) {
                if (!pp[s2]) continue;
                float ax, ay;
                if ((s2 & 1) == 0) { ax = acc[t][s2>>1][0]; ay = acc[t][s2>>1][1]; }
                else               { ax = acc[t][s2>>1][2]; ay = acc[t][s2>>1][3]; }
                float vx = fmaxf(ax + bb.x, 0.f);
                float vy = fmaxf(ay + bb.y, 0.f);
                float2 id;
                if (IDIN == 0) {
                    id = *(const float2*)(identityf + (size_t)rr[s2] * DDIM + c);
                } else {
                    int lr2 = rowgrp * 32 + g + s2 * 8;
                    unsigned iv = smA[lr2 * AWW + 64 + (c >> 4) * 8
                                      + 2 * ((c >> 1) & 3) + ((c >> 3) & 1)];
                    id = __half22float2(*(__half2*)&iv);
                }
                *(unsigned*)(out + (size_t)rr[s2] * DDIM + c) = cvt2(vx + id.x, vy + id.y);
            }
        }
    } else {
        float* out = (float*)outv;
        float ss[4] = {0.f, 0.f, 0.f, 0.f};
#pragma unroll
        for (int t = 0; t < 4; t++) {
            const int c = colq * 32 + t * 8 + tig * 2;
            float2 bb = *(const float2*)(bias + c);
#pragma unroll
            for (int s = 0; s < 2; s++) {
                acc[t][s][0] += bb.x; acc[t][s][1] += bb.y;
                acc[t][s][2] += bb.x; acc[t][s][3] += bb.y;
                ss[2*s]   += acc[t][s][0] * acc[t][s][0] + acc[t][s][1] * acc[t][s][1];
                ss[2*s+1] += acc[t][s][2] * acc[t][s][2] + acc[t][s][3] * acc[t][s][3];
            }
        }
#pragma unroll
        for (int i = 0; i < 4; i++) {
            ss[i] += __shfl_xor_sync(0xffffffffu, ss[i], 1);
            ss[i] += __shfl_xor_sync(0xffffffffu, ss[i], 2);
        }
        __syncthreads();
        if (tig == 0) {
#pragma unroll
            for (int i = 0; i < 4; i++) s_red[colq][rowgrp][i * 8 + g] = ss[i];
        }
        __syncthreads();
        float inv[4];
#pragma unroll
        for (int i = 0; i < 4; i++) {
            float tot = s_red[0][rowgrp][i * 8 + g] + s_red[1][rowgrp][i * 8 + g]
                      + s_red[2][rowgrp][i * 8 + g] + s_red[3][rowgrp][i * 8 + g];
            inv[i] = 1.f / fmaxf(sqrtf(tot), 1e-12f);
        }
#pragma unroll
        for (int t = 0; t < 4; t++) {
            const int c = colq * 32 + t * 8 + tig * 2;
#pragma unroll
            for (int s = 0; s < 2; s++) {
                if (pp[2*s])
                    *(float2*)(out + (size_t)rr[2*s] * DDIM + c) =
                        make_float2(acc[t][s][0] * inv[2*s], acc[t][s][1] * inv[2*s]);
                if (pp[2*s+1])
                    *(float2*)(out + (size_t)rr[2*s+1] * DDIM + c) =
                        make_float2(acc[t][s][2] * inv[2*s+1], acc[t][s][3] * inv[2*s+1]);
            }
        }
    }
}

#define SM1 (128 * 72 * 4)     // 36.9 KB
#define SM2 (128 * 136 * 4)    // 69.6 KB

// ---------------- launch ----------------
extern "C" void kernel_launch(void* const* d_in, const int* in_sizes, int n_in,
                              void* d_out, int out_size) {
    const float* x      = (const float*)d_in[0];
    const void*  ei     = d_in[1];
    const float* W_proj = (const float*)d_in[2];
    const float* W1_l   = (const float*)d_in[3];
    const float* b1     = (const float*)d_in[4];
    const float* W1_r   = (const float*)d_in[5];
    const float* W2_l   = (const float*)d_in[6];
    const float* b2     = (const float*)d_in[7];
    const float* W2_r   = (const float*)d_in[8];
    const float* W3_l   = (const float*)d_in[9];
    const float* b3     = (const float*)d_in[10];
    const float* W3_r   = (const float*)d_in[11];
    float* out = (float*)d_out;

    __half *bufA, *bufB;
    unsigned *Wp, *Wb;
    cudaGetSymbolAddress((void**)&bufA, g_bufA);
    cudaGetSymbolAddress((void**)&bufB, g_bufB);
    cudaGetSymbolAddress((void**)&Wp,   g_Wp);
    cudaGetSymbolAddress((void**)&Wb,   g_Wb);
    unsigned* Wb0 = Wb;
    unsigned* Wb1 = Wb + DDIM * 16 * 8;
    unsigned* Wb2 = Wb + 2 * DDIM * 16 * 8;

    static int attr_done = 0;
    if (!attr_done) {
        cudaFuncSetAttribute(k_gemm_proj,     cudaFuncAttributeMaxDynamicSharedMemorySize, SM1);
        cudaFuncSetAttribute(k_gemm_agg<1,0>, cudaFuncAttributeMaxDynamicSharedMemorySize, SM2);
        cudaFuncSetAttribute(k_gemm_agg<1,2>, cudaFuncAttributeMaxDynamicSharedMemorySize, SM2);
        cudaFuncSetAttribute(k_gemm_agg<2,0>, cudaFuncAttributeMaxDynamicSharedMemorySize, SM2);
        attr_done = 1;
    }

    // 1: fused weight conversion
    ConvArgs ca;
    ca.src[0] = W_proj; ca.dst[0] = Wp;  ca.koff[0] = 0;   ca.kfull[0] = 128;
    ca.src[1] = W1_l;   ca.dst[1] = Wb0; ca.koff[1] = 0;   ca.kfull[1] = 256;
    ca.src[2] = W1_r;   ca.dst[2] = Wb0; ca.koff[2] = 128; ca.kfull[2] = 256;
    ca.src[3] = W2_l;   ca.dst[3] = Wb1; ca.koff[3] = 0;   ca.kfull[3] = 256;
    ca.src[4] = W2_r;   ca.dst[4] = Wb1; ca.koff[4] = 128; ca.kfull[4] = 256;
    ca.src[5] = W3_l;   ca.dst[5] = Wb2; ca.koff[5] = 0;   ca.kfull[5] = 256;
    ca.src[6] = W3_r;   ca.dst[6] = Wb2; ca.koff[6] = 128; ca.kfull[6] = 256;
    k_convert_all<<<dim3(64, 7), 256>>>(ca);

    // 2: init deg + prefix dtype detect
    k_init<<<SBLK, 256>>>((const unsigned*)ei);

    // 3: degree histogram
    k_hist<<<(EE + 255) / 256, 256>>>(ei);

    // 4: proj GEMM (profiled slot): h0 = x @ Wproj^T
    k_gemm_proj<<<NBLK, 512, SM1>>>(x, Wp, bufA);

    // 5-7: parallel scan
    k_scan1<<<SBLK, 256>>>();
    k_scan2<<<1, 512>>>();
    k_scan3<<<SBLK, 256>>>();

    // 8: CSR fill
    k_fill<<<(EE + 255) / 256, 256>>>(ei);

    // layer 1: h1 = relu([mean(h0)|h0] @ W1 + b1) + x
    k_gemm_agg<1, 0><<<NBLK, 512, SM2>>>(bufA, Wb0, b1, x, bufB);

    // layer 2: h2 = relu([mean(h1)|h1] @ W2 + b2) + h1
    k_gemm_agg<1, 2><<<NBLK, 512, SM2>>>(bufB, Wb1, b2, nullptr, bufA);

    // layer 3: out = normalize([mean(h2)|h2] @ W3 + b3)
    k_gemm_agg<2, 0><<<NBLK, 512, SM2>>>(bufA, Wb2, b3, nullptr, out);
}

// round 15
// speedup vs baseline: 1.0966x; 1.0966x over previous
#include <cuda_runtime.h>
#include <cuda_fp16.h>
#include <stdint.h>
#include <math.h>

#define NN   100000
#define EE   800000
#define DDIM 128
#define NBLK 782      // 782*128 = 100096 rows
#define SBLK 391      // scan blocks: 391*256 >= NN

// ---------------- scratch (device globals; no runtime alloc) ----------------
__device__ __align__(256) __half g_bufA[(size_t)NBLK * 128 * DDIM];
__device__ __align__(256) __half g_bufB[(size_t)NBLK * 128 * DDIM];
__device__ int   g_deg[NN];
__device__ int   g_rowptr[NN + 1];
__device__ int   g_cursor[NN];
__device__ float g_deginv[NN];
__device__ int   g_colidx[EE];
__device__ int   g_part[512];
__device__ int   g_is64;
// fragment-packed fp16 weights (hi only), kstep-paired warp-contiguous:
// uint4 idx = ((n8*(KCH/2) + kp)*8 + g)*4 + tig ; uint4 = {ksf_even h0, h1, ksf_odd h0, h1}
__device__ __align__(16) unsigned g_Wp[DDIM * 8 * 8];         // proj  KCH=8
__device__ __align__(16) unsigned g_Wb[3][DDIM * 16 * 8];     // layers KCH=16

// ---------------- init + prefix dtype detect ----------------
__global__ void k_init(const unsigned* __restrict__ w) {
    int i = blockIdx.x * blockDim.x + threadIdx.x;
    if (i < NN) g_deg[i] = 0;
    if (blockIdx.x == 0) {
        if (threadIdx.x == 0) g_is64 = 1;
        __syncthreads();
        unsigned acc = 0;
#pragma unroll
        for (int k = 0; k < 16; k++)
            acc |= w[2 * (threadIdx.x + k * 256) + 1];
        if (acc != 0) g_is64 = 0;
    }
}
__device__ __forceinline__ int load_idx(const void* ei, int pos, int is64) {
    if (is64) return (int)((const long long*)ei)[pos];
    return ((const int*)ei)[pos];
}
__global__ void k_hist(const void* __restrict__ ei) {
    int e = blockIdx.x * blockDim.x + threadIdx.x;
    if (e < EE) {
        int d = load_idx(ei, EE + e, g_is64);
        if ((unsigned)d < NN) atomicAdd(&g_deg[d], 1);
    }
}

// ---------------- parallel 3-phase exclusive scan ----------------
__global__ void k_scan1() {
    __shared__ int sh[256];
    int t = threadIdx.x;
    int i = blockIdx.x * 256 + t;
    sh[t] = (i < NN) ? g_deg[i] : 0;
    __syncthreads();
#pragma unroll
    for (int off = 128; off > 0; off >>= 1) {
        if (t < off) sh[t] += sh[t + off];
        __syncthreads();
    }
    if (t == 0) g_part[blockIdx.x] = sh[0];
}
__global__ void k_scan2() {
    __shared__ int sh[512];
    int t = threadIdx.x;
    int v = (t < SBLK) ? g_part[t] : 0;
    sh[t] = v;
    __syncthreads();
#pragma unroll
    for (int off = 1; off < 512; off <<= 1) {
        int u = (t >= off) ? sh[t - off] : 0;
        __syncthreads();
        sh[t] += u;
        __syncthreads();
    }
    if (t < SBLK) g_part[t] = sh[t] - v;
    if (t == SBLK - 1) g_rowptr[NN] = sh[t];
}
__global__ void k_scan3() {
    __shared__ int sh[256];
    int t = threadIdx.x;
    int i = blockIdx.x * 256 + t;
    int d = (i < NN) ? g_deg[i] : 0;
    sh[t] = d;
    __syncthreads();
#pragma unroll
    for (int off = 1; off < 256; off <<= 1) {
        int u = (t >= off) ? sh[t - off] : 0;
        __syncthreads();
        sh[t] += u;
        __syncthreads();
    }
    if (i < NN) {
        int excl = sh[t] - d + g_part[blockIdx.x];
        g_rowptr[i] = excl;
        g_cursor[i] = excl;
        g_deginv[i] = (d > 0) ? 1.0f / (float)d : 0.0f;
    }
}
__global__ void k_fill(const void* __restrict__ ei) {
    int e = blockIdx.x * blockDim.x + threadIdx.x;
    if (e < EE) {
        int is64 = g_is64;
        int s = load_idx(ei, e, is64);
        int d = load_idx(ei, EE + e, is64);
        if ((unsigned)d < NN && (unsigned)s < NN) {
            int p = atomicAdd(&g_cursor[d], 1);
            g_colidx[p] = s;
        }
    }
}

// ---------------- weight conversion: fp32 -> kstep-paired fp16 fragments ----------------
struct ConvArgs {
    const float*  src[7];
    unsigned*     dst[7];
    int           koff[7];
    int           kfull[7];
};
__global__ void k_convert_all(ConvArgs a) {
    int m = blockIdx.y;
    int idx = blockIdx.x * blockDim.x + threadIdx.x;
    if (idx >= DDIM * DDIM) return;
    int n = idx >> 7, k = idx & 127;
    __half h = __float2half_rn(a.src[m][idx]);
    int kg   = a.koff[m] + k;
    int ksf  = kg >> 4;
    int kp   = ksf >> 1;
    int ko   = ksf & 1;
    int kpos = kg & 15;
    int tig  = (kpos >> 1) & 3;
    int hf   = (kpos >> 3) & 1;
    int b    = kpos & 1;
    unsigned u4 = (((unsigned)((n >> 3) * (a.kfull[m] >> 5) + kp) * 8 + (n & 7)) * 4 + tig);
    ((__half*)a.dst[m])[(u4 * 4 + ko * 2 + hf) * 2 + b] = h;
}

// ---------------- common GEMM pieces ----------------
__device__ __forceinline__ unsigned cvt2(float x, float y) {
    __half2 t = __floats2half2_rn(x, y);
    return *reinterpret_cast<unsigned*>(&t);
}
__device__ __forceinline__ void mma_f16(float (&c)[4], const unsigned (&a)[4],
                                        unsigned b0, unsigned b1) {
    asm volatile(
        "mma.sync.aligned.m16n8k16.row.col.f32.f16.f16.f32 "
        "{%0,%1,%2,%3}, {%4,%5,%6,%7}, {%8,%9}, {%0,%1,%2,%3};\n"
        : "+f"(c[0]), "+f"(c[1]), "+f"(c[2]), "+f"(c[3])
        : "r"(a[0]), "r"(a[1]), "r"(a[2]), "r"(a[3]), "r"(b0), "r"(b1));
}
// A smem (R12 layout): 128 rows x (KH*128) k fp16, word stride AWW = KH*64 + 4
// word(row, k) = row*AWW + (k>>4)*8 + ((k&15)>>1)

// ---------------- proj GEMM (KH=1, fp32 A in, fp16 out) ----------------
__global__ void __launch_bounds__(512, 2) k_gemm_proj(
    const float* __restrict__ A0, const unsigned* __restrict__ Bfrag,
    __half* __restrict__ out)
{
    constexpr int KCH = 8;
    constexpr int AWW = 68;
    extern __shared__ unsigned smA[];
    const int tid = threadIdx.x;
    const int w = tid >> 5;
    const int lane = tid & 31;
    const int g = lane >> 2;
    const int tig = lane & 3;
    const int rowgrp = w & 3;
    const int colq = w >> 2;
    const int rowbase = blockIdx.x * 128 + rowgrp * 32;
    int rr[4] = { rowbase + g, rowbase + g + 8, rowbase + g + 16, rowbase + g + 24 };
    bool pp[4];
#pragma unroll
    for (int i = 0; i < 4; i++) pp[i] = rr[i] < NN;

    const uint4* Bf = (const uint4*)Bfrag;
    const int bbase0 = (colq * 4 * (KCH / 2)) * 32 + g * 4 + tig;

    // stage A (R12): coalesced lane-contiguous loads, uint2 STS
#pragma unroll
    for (int it = 0; it < 8; it++) {
        int idx = it * 512 + tid;
        int row = idx >> 5, l = idx & 31;
        int grow = blockIdx.x * 128 + row;
        float4 fv = make_float4(0.f, 0.f, 0.f, 0.f);
        if (grow < NN) fv = *(const float4*)(A0 + (size_t)grow * DDIM + l * 4);
        uint2 st;
        st.x = cvt2(fv.x, fv.y);
        st.y = cvt2(fv.z, fv.w);
        *(uint2*)&smA[row * AWW + (l >> 2) * 8 + (l & 3) * 2] = st;
    }
    __syncthreads();

    const unsigned* ar = smA + (rowgrp * 32 + g) * AWW + tig;
    float acc[4][2][4];
#pragma unroll
    for (int t = 0; t < 4; t++)
#pragma unroll
        for (int s = 0; s < 2; s++)
#pragma unroll
            for (int i = 0; i < 4; i++) acc[t][s][i] = 0.f;

#pragma unroll
    for (int kp = 0; kp < KCH / 2; kp++) {
        uint4 bb[4];
#pragma unroll
        for (int t = 0; t < 4; t++)
            bb[t] = Bf[bbase0 + (t * (KCH / 2) + kp) * 32];
#pragma unroll
        for (int sub = 0; sub < 2; sub++) {
            const int ksf = kp * 2 + sub;
            unsigned aH[2][4];
            aH[0][0] = ar[ksf * 8];
            aH[0][1] = ar[8 * AWW + ksf * 8];
            aH[0][2] = ar[ksf * 8 + 4];
            aH[0][3] = ar[8 * AWW + ksf * 8 + 4];
            aH[1][0] = ar[16 * AWW + ksf * 8];
            aH[1][1] = ar[24 * AWW + ksf * 8];
            aH[1][2] = ar[16 * AWW + ksf * 8 + 4];
            aH[1][3] = ar[24 * AWW + ksf * 8 + 4];
#pragma unroll
            for (int t = 0; t < 4; t++) {
                unsigned b0 = sub ? bb[t].z : bb[t].x;
                unsigned b1 = sub ? bb[t].w : bb[t].y;
                mma_f16(acc[t][0], aH[0], b0, b1);
                mma_f16(acc[t][1], aH[1], b0, b1);
            }
        }
    }
#pragma unroll
    for (int t = 0; t < 4; t++) {
        const int c = colq * 32 + t * 8 + tig * 2;
#pragma unroll
        for (int s = 0; s < 2; s++) {
            if (pp[2*s])
                *(unsigned*)(out + (size_t)rr[2*s] * DDIM + c) = cvt2(acc[t][s][0], acc[t][s][1]);
            if (pp[2*s+1])
                *(unsigned*)(out + (size_t)rr[2*s+1] * DDIM + c) = cvt2(acc[t][s][2], acc[t][s][3]);
        }
    }
}

// ---------------- fused layer GEMM: gather-mean + [mean|h] @ W^T + epilogue ----------------
// EPI: 1 = relu(acc+bias)+identity, 2 = bias + L2-norm -> fp32
// IDIN: 0 = identity fp32 global, 2 = identity = h (smem A1 panel)
template<int EPI, int IDIN>
__global__ void __launch_bounds__(512, 2) k_gemm_agg(
    const __half* __restrict__ H, const unsigned* __restrict__ Bfrag,
    const float* __restrict__ bias, const float* __restrict__ identityf,
    void* __restrict__ outv)
{
    constexpr int KCH = 16;
    constexpr int AWW = 132;
    extern __shared__ unsigned smA[];
    __shared__ float s_red[4][4][32];

    const int tid = threadIdx.x;
    const int w = tid >> 5;
    const int lane = tid & 31;
    const int g = lane >> 2;
    const int tig = lane & 3;
    const int rowgrp = w & 3;
    const int colq = w >> 2;
    const int rowbase = blockIdx.x * 128 + rowgrp * 32;
    int rr[4] = { rowbase + g, rowbase + g + 8, rowbase + g + 16, rowbase + g + 24 };
    bool pp[4];
#pragma unroll
    for (int i = 0; i < 4; i++) pp[i] = rr[i] < NN;

    const uint4* Bf = (const uint4*)Bfrag;
    const int bbase0 = (colq * 4 * (KCH / 2)) * 32 + g * 4 + tig;

    // ---- A1 (R12): own h rows (k 128..255), contiguous uint4 copy ----
#pragma unroll
    for (int it = 0; it < 4; it++) {
        int idx = it * 512 + tid;
        int row = idx >> 4, l = idx & 15;
        int grow = blockIdx.x * 128 + row;
        uint4 v = make_uint4(0u, 0u, 0u, 0u);
        if (grow < NN) v = *(const uint4*)(H + (size_t)grow * DDIM + l * 8);
        *(uint4*)&smA[row * AWW + 64 + (l >> 1) * 8 + (l & 1) * 4] = v;
    }

    // ---- A0 (R12): gather-mean, warp w handles 8 nodes, MLP=8 ----
#pragma unroll 1
    for (int i = 0; i < 8; i++) {
        int lr = w * 8 + i;
        int node = blockIdx.x * 128 + lr;
        float4 a0 = make_float4(0.f, 0.f, 0.f, 0.f);
        float4 a1 = make_float4(0.f, 0.f, 0.f, 0.f);
        float4 a2 = make_float4(0.f, 0.f, 0.f, 0.f);
        float4 a3 = make_float4(0.f, 0.f, 0.f, 0.f);
        float sc = 0.f;
        if (node < NN) {
            int s = g_rowptr[node], e = g_rowptr[node + 1];
            sc = g_deginv[node];
            int j = s;
            for (; j + 8 <= e; j += 8) {
                uint2 v[8];
#pragma unroll
                for (int k = 0; k < 8; k++)
                    v[k] = *(const uint2*)(H + (size_t)g_colidx[j + k] * DDIM + lane * 4);
#pragma unroll
                for (int k = 0; k < 8; k++) {
                    float2 p0 = __half22float2(*(__half2*)&v[k].x);
                    float2 p1 = __half22float2(*(__half2*)&v[k].y);
                    float4* a = (k & 3) == 0 ? &a0 : (k & 3) == 1 ? &a1 : (k & 3) == 2 ? &a2 : &a3;
                    a->x += p0.x; a->y += p0.y; a->z += p1.x; a->w += p1.y;
                }
            }
            if (j + 4 <= e) {
                uint2 v[4];
#pragma unroll
                for (int k = 0; k < 4; k++)
                    v[k] = *(const uint2*)(H + (size_t)g_colidx[j + k] * DDIM + lane * 4);
#pragma unroll
                for (int k = 0; k < 4; k++) {
                    float2 p0 = __half22float2(*(__half2*)&v[k].x);
                    float2 p1 = __half22float2(*(__half2*)&v[k].y);
                    float4* a = k == 0 ? &a0 : k == 1 ? &a1 : k == 2 ? &a2 : &a3;
                    a->x += p0.x; a->y += p0.y; a->z += p1.x; a->w += p1.y;
                }
                j += 4;
            }
            for (; j < e; j++) {
                uint2 v0 = *(const uint2*)(H + (size_t)g_colidx[j] * DDIM + lane * 4);
                float2 p0 = __half22float2(*(__half2*)&v0.x);
                float2 p1 = __half22float2(*(__half2*)&v0.y);
                a0.x += p0.x; a0.y += p0.y; a0.z += p1.x; a0.w += p1.y;
            }
        }
        uint2 st;
        st.x = cvt2((a0.x + a1.x + a2.x + a3.x) * sc, (a0.y + a1.y + a2.y + a3.y) * sc);
        st.y = cvt2((a0.z + a1.z + a2.z + a3.z) * sc, (a0.w + a1.w + a2.w + a3.w) * sc);
        *(uint2*)&smA[lr * AWW + (lane >> 2) * 8 + (lane & 3) * 2] = st;
    }
    __syncthreads();

    const unsigned* ar = smA + (rowgrp * 32 + g) * AWW + tig;
    float acc[4][2][4];
#pragma unroll
    for (int t = 0; t < 4; t++)
#pragma unroll
        for (int s = 0; s < 2; s++)
#pragma unroll
            for (int i = 0; i < 4; i++) acc[t][s][i] = 0.f;

#pragma unroll
    for (int kp = 0; kp < KCH / 2; kp++) {
        uint4 bb[4];
#pragma unroll
        for (int t = 0; t < 4; t++)
            bb[t] = Bf[bbase0 + (t * (KCH / 2) + kp) * 32];
#pragma unroll
        for (int sub = 0; sub < 2; sub++) {
            const int ksf = kp * 2 + sub;
            unsigned aH[2][4];
            aH[0][0] = ar[ksf * 8];
            aH[0][1] = ar[8 * AWW + ksf * 8];
            aH[0][2] = ar[ksf * 8 + 4];
            aH[0][3] = ar[8 * AWW + ksf * 8 + 4];
            aH[1][0] = ar[16 * AWW + ksf * 8];
            aH[1][1] = ar[24 * AWW + ksf * 8];
            aH[1][2] = ar[16 * AWW + ksf * 8 + 4];
            aH[1][3] = ar[24 * AWW + ksf * 8 + 4];
#pragma unroll
            for (int t = 0; t < 4; t++) {
                unsigned b0 = sub ? bb[t].z : bb[t].x;
                unsigned b1 = sub ? bb[t].w : bb[t].y;
                mma_f16(acc[t][0], aH[0], b0, b1);
                mma_f16(acc[t][1], aH[1], b0, b1);
            }
        }
    }

    if (EPI == 1) {
        __half* out = (__half*)outv;
#pragma unroll
        for (int t = 0; t < 4; t++) {
            const int c = colq * 32 + t * 8 + tig * 2;
            float2 bb = *(const float2*)(bias + c);
#pragma unroll
            for (int s2 = 0; s2 < 4; s2++) {
                if (!pp[s2]) continue;
                float ax, ay;
                if ((s2 & 1) == 0) { ax = acc[t][s2>>1][0]; ay = acc[t][s2>>1][1]; }
                else               { ax = acc[t][s2>>1][2]; ay = acc[t][s2>>1][3]; }
                float vx = fmaxf(ax + bb.x, 0.f);
                float vy = fmaxf(ay + bb.y, 0.f);
                float2 id;
                if (IDIN == 0) {
                    id = *(const float2*)(identityf + (size_t)rr[s2] * DDIM + c);
                } else {
                    int lr2 = rowgrp * 32 + g + s2 * 8;
                    unsigned iv = smA[lr2 * AWW + 64 + (c >> 4) * 8 + ((c & 15) >> 1)];
                    id = __half22float2(*(__half2*)&iv);
                }
                *(unsigned*)(out + (size_t)rr[s2] * DDIM + c) = cvt2(vx + id.x, vy + id.y);
            }
        }
    } else {
        float* out = (float*)outv;
        float ss[4] = {0.f, 0.f, 0.f, 0.f};
#pragma unroll
        for (int t = 0; t < 4; t++) {
            const int c = colq * 32 + t * 8 + tig * 2;
            float2 bb = *(const float2*)(bias + c);
#pragma unroll
            for (int s = 0; s < 2; s++) {
                acc[t][s][0] += bb.x; acc[t][s][1] += bb.y;
                acc[t][s][2] += bb.x; acc[t][s][3] += bb.y;
                ss[2*s]   += acc[t][s][0] * acc[t][s][0] + acc[t][s][1] * acc[t][s][1];
                ss[2*s+1] += acc[t][s][2] * acc[t][s][2] + acc[t][s][3] * acc[t][s][3];
            }
        }
#pragma unroll
        for (int i = 0; i < 4; i++) {
            ss[i] += __shfl_xor_sync(0xffffffffu, ss[i], 1);
            ss[i] += __shfl_xor_sync(0xffffffffu, ss[i], 2);
        }
        __syncthreads();
        if (tig == 0) {
#pragma unroll
            for (int i = 0; i < 4; i++) s_red[colq][rowgrp][i * 8 + g] = ss[i];
        }
        __syncthreads();
        float inv[4];
#pragma unroll
        for (int i = 0; i < 4; i++) {
            float tot = s_red[0][rowgrp][i * 8 + g] + s_red[1][rowgrp][i * 8 + g]
                      + s_red[2][rowgrp][i * 8 + g] + s_red[3][rowgrp][i * 8 + g];
            inv[i] = 1.f / fmaxf(sqrtf(tot), 1e-12f);
        }
#pragma unroll
        for (int t = 0; t < 4; t++) {
            const int c = colq * 32 + t * 8 + tig * 2;
#pragma unroll
            for (int s = 0; s < 2; s++) {
                if (pp[2*s])
                    *(float2*)(out + (size_t)rr[2*s] * DDIM + c) =
                        make_float2(acc[t][s][0] * inv[2*s], acc[t][s][1] * inv[2*s]);
                if (pp[2*s+1])
                    *(float2*)(out + (size_t)rr[2*s+1] * DDIM + c) =
                        make_float2(acc[t][s][2] * inv[2*s+1], acc[t][s][3] * inv[2*s+1]);
            }
        }
    }
}

#define SM1 (128 * 68 * 4)    // KH=1 A panel (34.8 KB)
#define SM2 (128 * 132 * 4)   // KH=2 A panel (67.6 KB)

// ---------------- launch ----------------
extern "C" void kernel_launch(void* const* d_in, const int* in_sizes, int n_in,
                              void* d_out, int out_size) {
    const float* x      = (const float*)d_in[0];
    const void*  ei     = d_in[1];
    const float* W_proj = (const float*)d_in[2];
    const float* W1_l   = (const float*)d_in[3];
    const float* b1     = (const float*)d_in[4];
    const float* W1_r   = (const float*)d_in[5];
    const float* W2_l   = (const float*)d_in[6];
    const float* b2     = (const float*)d_in[7];
    const float* W2_r   = (const float*)d_in[8];
    const float* W3_l   = (const float*)d_in[9];
    const float* b3     = (const float*)d_in[10];
    const float* W3_r   = (const float*)d_in[11];
    float* out = (float*)d_out;

    __half *bufA, *bufB;
    unsigned *Wp, *Wb;
    cudaGetSymbolAddress((void**)&bufA, g_bufA);
    cudaGetSymbolAddress((void**)&bufB, g_bufB);
    cudaGetSymbolAddress((void**)&Wp,   g_Wp);
    cudaGetSymbolAddress((void**)&Wb,   g_Wb);
    unsigned* Wb0 = Wb;
    unsigned* Wb1 = Wb + DDIM * 16 * 8;
    unsigned* Wb2 = Wb + 2 * DDIM * 16 * 8;

    static int attr_done = 0;
    if (!attr_done) {
        cudaFuncSetAttribute(k_gemm_proj,     cudaFuncAttributeMaxDynamicSharedMemorySize, SM1);
        cudaFuncSetAttribute(k_gemm_agg<1,0>, cudaFuncAttributeMaxDynamicSharedMemorySize, SM2);
        cudaFuncSetAttribute(k_gemm_agg<1,2>, cudaFuncAttributeMaxDynamicSharedMemorySize, SM2);
        cudaFuncSetAttribute(k_gemm_agg<2,0>, cudaFuncAttributeMaxDynamicSharedMemorySize, SM2);
        attr_done = 1;
    }

    // 1: fused weight conversion (kstep-paired fragments)
    ConvArgs ca;
    ca.src[0] = W_proj; ca.dst[0] = Wp;  ca.koff[0] = 0;   ca.kfull[0] = 128;
    ca.src[1] = W1_l;   ca.dst[1] = Wb0; ca.koff[1] = 0;   ca.kfull[1] = 256;
    ca.src[2] = W1_r;   ca.dst[2] = Wb0; ca.koff[2] = 128; ca.kfull[2] = 256;
    ca.src[3] = W2_l;   ca.dst[3] = Wb1; ca.koff[3] = 0;   ca.kfull[3] = 256;
    ca.src[4] = W2_r;   ca.dst[4] = Wb1; ca.koff[4] = 128; ca.kfull[4] = 256;
    ca.src[5] = W3_l;   ca.dst[5] = Wb2; ca.koff[5] = 0;   ca.kfull[5] = 256;
    ca.src[6] = W3_r;   ca.dst[6] = Wb2; ca.koff[6] = 128; ca.kfull[6] = 256;
    k_convert_all<<<dim3(64, 7), 256>>>(ca);

    // 2: init deg + prefix dtype detect
    k_init<<<SBLK, 256>>>((const unsigned*)ei);

    // 3: degree histogram
    k_hist<<<(EE + 255) / 256, 256>>>(ei);

    // 4: proj GEMM (profiled slot): h0 = x @ Wproj^T
    k_gemm_proj<<<NBLK, 512, SM1>>>(x, Wp, bufA);

    // 5-7: parallel scan
    k_scan1<<<SBLK, 256>>>();
    k_scan2<<<1, 512>>>();
    k_scan3<<<SBLK, 256>>>();

    // 8: CSR fill
    k_fill<<<(EE + 255) / 256, 256>>>(ei);

    // layer 1: h1 = relu([mean(h0)|h0] @ W1 + b1) + x
    k_gemm_agg<1, 0><<<NBLK, 512, SM2>>>(bufA, Wb0, b1, x, bufB);

    // layer 2: h2 = relu([mean(h1)|h1] @ W2 + b2) + h1
    k_gemm_agg<1, 2><<<NBLK, 512, SM2>>>(bufB, Wb1, b2, nullptr, bufA);

    // layer 3: out = normalize([mean(h2)|h2] @ W3 + b3)
    k_gemm_agg<2, 0><<<NBLK, 512, SM2>>>(bufA, Wb2, b3, nullptr, out);
}

// round 16
// speedup vs baseline: 1.1942x; 1.0889x over previous
#include <cuda_runtime.h>
#include <cuda_fp16.h>
#include <stdint.h>
#include <math.h>

#define NN   100000
#define EE   800000
#define DDIM 128
#define NBLK 782      // 782*128 = 100096 rows
#define SBLK 391      // scan blocks: 391*256 >= NN

// ---------------- scratch (device globals; no runtime alloc) ----------------
__device__ __align__(256) __half g_bufA[(size_t)NBLK * 128 * DDIM];
__device__ __align__(256) __half g_bufB[(size_t)NBLK * 128 * DDIM];
__device__ int   g_deg[NN];
__device__ int   g_rowptr[NN + 1];
__device__ int   g_cursor[NN];
__device__ float g_deginv[NN];
__device__ int   g_colidx[EE];
__device__ int   g_part[512];
__device__ int   g_is64;
// fragment-packed fp16 weights (hi only), warp-contiguous (R12 layout):
// u32 idx = (((nb*KCH + ksf)*8 + g)*4 + tig)*2 + half   (n = nb*8+g)
__device__ __align__(16) unsigned g_Wp[DDIM * 8 * 8];         // proj  KCH=8
__device__ __align__(16) unsigned g_Wb[3][DDIM * 16 * 8];     // layers KCH=16

// ---------------- init + prefix dtype detect ----------------
__global__ void k_init(const unsigned* __restrict__ w) {
    int i = blockIdx.x * blockDim.x + threadIdx.x;
    if (i < NN) g_deg[i] = 0;
    if (blockIdx.x == 0) {
        if (threadIdx.x == 0) g_is64 = 1;
        __syncthreads();
        unsigned acc = 0;
#pragma unroll
        for (int k = 0; k < 16; k++)
            acc |= w[2 * (threadIdx.x + k * 256) + 1];
        if (acc != 0) g_is64 = 0;
    }
}
__device__ __forceinline__ int load_idx(const void* ei, int pos, int is64) {
    if (is64) return (int)((const long long*)ei)[pos];
    return ((const int*)ei)[pos];
}
__global__ void k_hist(const void* __restrict__ ei) {
    int e = blockIdx.x * blockDim.x + threadIdx.x;
    if (e < EE) {
        int d = load_idx(ei, EE + e, g_is64);
        if ((unsigned)d < NN) atomicAdd(&g_deg[d], 1);
    }
}

// ---------------- parallel 3-phase exclusive scan ----------------
__global__ void k_scan1() {
    __shared__ int sh[256];
    int t = threadIdx.x;
    int i = blockIdx.x * 256 + t;
    sh[t] = (i < NN) ? g_deg[i] : 0;
    __syncthreads();
#pragma unroll
    for (int off = 128; off > 0; off >>= 1) {
        if (t < off) sh[t] += sh[t + off];
        __syncthreads();
    }
    if (t == 0) g_part[blockIdx.x] = sh[0];
}
__global__ void k_scan2() {
    __shared__ int sh[512];
    int t = threadIdx.x;
    int v = (t < SBLK) ? g_part[t] : 0;
    sh[t] = v;
    __syncthreads();
#pragma unroll
    for (int off = 1; off < 512; off <<= 1) {
        int u = (t >= off) ? sh[t - off] : 0;
        __syncthreads();
        sh[t] += u;
        __syncthreads();
    }
    if (t < SBLK) g_part[t] = sh[t] - v;
    if (t == SBLK - 1) g_rowptr[NN] = sh[t];
}
__global__ void k_scan3() {
    __shared__ int sh[256];
    int t = threadIdx.x;
    int i = blockIdx.x * 256 + t;
    int d = (i < NN) ? g_deg[i] : 0;
    sh[t] = d;
    __syncthreads();
#pragma unroll
    for (int off = 1; off < 256; off <<= 1) {
        int u = (t >= off) ? sh[t - off] : 0;
        __syncthreads();
        sh[t] += u;
        __syncthreads();
    }
    if (i < NN) {
        int excl = sh[t] - d + g_part[blockIdx.x];
        g_rowptr[i] = excl;
        g_cursor[i] = excl;
        g_deginv[i] = (d > 0) ? 1.0f / (float)d : 0.0f;
    }
}
__global__ void k_fill(const void* __restrict__ ei) {
    int e = blockIdx.x * blockDim.x + threadIdx.x;
    if (e < EE) {
        int is64 = g_is64;
        int s = load_idx(ei, e, is64);
        int d = load_idx(ei, EE + e, is64);
        if ((unsigned)d < NN && (unsigned)s < NN) {
            int p = atomicAdd(&g_cursor[d], 1);
            g_colidx[p] = s;
        }
    }
}

// ---------------- weight conversion: fp32 -> fragment-packed fp16 (R12 layout) ----------------
struct ConvArgs {
    const float*  src[7];
    unsigned*     dst[7];
    int           koff[7];
    int           kfull[7];
};
__global__ void k_convert_all(ConvArgs a) {
    int m = blockIdx.y;
    int idx = blockIdx.x * blockDim.x + threadIdx.x;
    if (idx >= DDIM * DDIM) return;
    int n = idx >> 7, k = idx & 127;
    __half h = __float2half_rn(a.src[m][idx]);
    int kg   = a.koff[m] + k;
    int ksf  = kg >> 4;
    int kpos = kg & 15;
    int tig  = (kpos >> 1) & 3;
    int hf   = kpos >> 3;
    int b    = kpos & 1;
    unsigned u32i = ((((unsigned)((n >> 3) * (a.kfull[m] >> 4) + ksf) * 8 + (n & 7)) * 4 + tig) * 2 + hf);
    ((__half*)a.dst[m])[u32i * 2 + b] = h;
}

// ---------------- common GEMM pieces ----------------
__device__ __forceinline__ unsigned cvt2(float x, float y) {
    __half2 t = __floats2half2_rn(x, y);
    return *reinterpret_cast<unsigned*>(&t);
}
__device__ __forceinline__ void mma_f16(float (&c)[4], const unsigned (&a)[4],
                                        unsigned b0, unsigned b1) {
    asm volatile(
        "mma.sync.aligned.m16n8k16.row.col.f32.f16.f16.f32 "
        "{%0,%1,%2,%3}, {%4,%5,%6,%7}, {%8,%9}, {%0,%1,%2,%3};\n"
        : "+f"(c[0]), "+f"(c[1]), "+f"(c[2]), "+f"(c[3])
        : "r"(a[0]), "r"(a[1]), "r"(a[2]), "r"(a[3]), "r"(b0), "r"(b1));
}
// A smem (R12): 128 rows x (KH*128) k fp16, word stride AWW = KH*64 + 4
// word(row, k) = row*AWW + (k>>4)*8 + ((k&15)>>1)

// ---------------- proj GEMM (KH=1, fp32 A in, fp16 out) — R12 verbatim ----------------
__global__ void __launch_bounds__(512, 2) k_gemm_proj(
    const float* __restrict__ A0, const unsigned* __restrict__ Bfrag,
    __half* __restrict__ out)
{
    constexpr int KCH = 8;
    constexpr int AWW = 68;
    extern __shared__ unsigned smA[];
    const int tid = threadIdx.x;
    const int w = tid >> 5;
    const int lane = tid & 31;
    const int g = lane >> 2;
    const int tig = lane & 3;
    const int rowgrp = w & 3;
    const int colq = w >> 2;
    const int rowbase = blockIdx.x * 128 + rowgrp * 32;
    int rr[4] = { rowbase + g, rowbase + g + 8, rowbase + g + 16, rowbase + g + 24 };
    bool pp[4];
#pragma unroll
    for (int i = 0; i < 4; i++) pp[i] = rr[i] < NN;

    const uint2* Bf = (const uint2*)Bfrag;
    const int bbase0 = (colq * 4 * KCH) * 32 + g * 4 + tig;

#pragma unroll
    for (int it = 0; it < 8; it++) {
        int idx = it * 512 + tid;
        int row = idx >> 5, l = idx & 31;
        int grow = blockIdx.x * 128 + row;
        float4 fv = make_float4(0.f, 0.f, 0.f, 0.f);
        if (grow < NN) fv = *(const float4*)(A0 + (size_t)grow * DDIM + l * 4);
        uint2 st;
        st.x = cvt2(fv.x, fv.y);
        st.y = cvt2(fv.z, fv.w);
        *(uint2*)&smA[row * AWW + (l >> 2) * 8 + (l & 3) * 2] = st;
    }
    __syncthreads();

    const unsigned* ar = smA + (rowgrp * 32 + g) * AWW + tig;
    float acc[4][2][4];
#pragma unroll
    for (int t = 0; t < 4; t++)
#pragma unroll
        for (int s = 0; s < 2; s++)
#pragma unroll
            for (int i = 0; i < 4; i++) acc[t][s][i] = 0.f;

#pragma unroll
    for (int ksf = 0; ksf < KCH; ksf++) {
        uint2 bb[4];
#pragma unroll
        for (int t = 0; t < 4; t++)
            bb[t] = Bf[bbase0 + (t * KCH + ksf) * 32];
        unsigned aH[2][4];
        aH[0][0] = ar[ksf * 8];
        aH[0][1] = ar[8 * AWW + ksf * 8];
        aH[0][2] = ar[ksf * 8 + 4];
        aH[0][3] = ar[8 * AWW + ksf * 8 + 4];
        aH[1][0] = ar[16 * AWW + ksf * 8];
        aH[1][1] = ar[24 * AWW + ksf * 8];
        aH[1][2] = ar[16 * AWW + ksf * 8 + 4];
        aH[1][3] = ar[24 * AWW + ksf * 8 + 4];
#pragma unroll
        for (int t = 0; t < 4; t++) {
            mma_f16(acc[t][0], aH[0], bb[t].x, bb[t].y);
            mma_f16(acc[t][1], aH[1], bb[t].x, bb[t].y);
        }
    }
#pragma unroll
    for (int t = 0; t < 4; t++) {
        const int c = colq * 32 + t * 8 + tig * 2;
#pragma unroll
        for (int s = 0; s < 2; s++) {
            if (pp[2*s])
                *(unsigned*)(out + (size_t)rr[2*s] * DDIM + c) = cvt2(acc[t][s][0], acc[t][s][1]);
            if (pp[2*s+1])
                *(unsigned*)(out + (size_t)rr[2*s+1] * DDIM + c) = cvt2(acc[t][s][2], acc[t][s][3]);
        }
    }
}

// ---------------- fused layer GEMM (R12 + dual-node interleaved gather) ----------------
// EPI: 1 = relu(acc+bias)+identity, 2 = bias + L2-norm -> fp32
// IDIN: 0 = identity fp32 global, 2 = identity = h (smem A1 panel)
template<int EPI, int IDIN>
__global__ void __launch_bounds__(512, 2) k_gemm_agg(
    const __half* __restrict__ H, const unsigned* __restrict__ Bfrag,
    const float* __restrict__ bias, const float* __restrict__ identityf,
    void* __restrict__ outv)
{
    constexpr int KCH = 16;
    constexpr int AWW = 132;
    extern __shared__ unsigned smA[];
    __shared__ float s_red[4][4][32];

    const int tid = threadIdx.x;
    const int w = tid >> 5;
    const int lane = tid & 31;
    const int g = lane >> 2;
    const int tig = lane & 3;
    const int rowgrp = w & 3;
    const int colq = w >> 2;
    const int rowbase = blockIdx.x * 128 + rowgrp * 32;
    int rr[4] = { rowbase + g, rowbase + g + 8, rowbase + g + 16, rowbase + g + 24 };
    bool pp[4];
#pragma unroll
    for (int i = 0; i < 4; i++) pp[i] = rr[i] < NN;

    const uint2* Bf = (const uint2*)Bfrag;
    const int bbase0 = (colq * 4 * KCH) * 32 + g * 4 + tig;

    // ---- A1: own h rows (k 128..255), contiguous uint4 copy (R12) ----
#pragma unroll
    for (int it = 0; it < 4; it++) {
        int idx = it * 512 + tid;
        int row = idx >> 4, l = idx & 15;
        int grow = blockIdx.x * 128 + row;
        uint4 v = make_uint4(0u, 0u, 0u, 0u);
        if (grow < NN) v = *(const uint4*)(H + (size_t)grow * DDIM + l * 8);
        *(uint4*)&smA[row * AWW + 64 + (l >> 1) * 8 + (l & 1) * 4] = v;
    }

    // ---- A0: gather-mean, warp w handles 8 nodes as 4 interleaved pairs ----
#pragma unroll 1
    for (int pi = 0; pi < 4; pi++) {
        int lr0 = w * 8 + pi * 2;
        int lr1 = lr0 + 1;
        int n0 = blockIdx.x * 128 + lr0;
        int n1 = n0 + 1;
        float4 a00 = make_float4(0.f,0.f,0.f,0.f), a01 = make_float4(0.f,0.f,0.f,0.f);
        float4 a10 = make_float4(0.f,0.f,0.f,0.f), a11 = make_float4(0.f,0.f,0.f,0.f);
        int j0 = 0, e0 = 0, j1 = 0, e1 = 0;
        float sc0 = 0.f, sc1 = 0.f;
        if (n0 < NN) { j0 = g_rowptr[n0]; e0 = g_rowptr[n0 + 1]; sc0 = g_deginv[n0]; }
        if (n1 < NN) { j1 = g_rowptr[n1]; e1 = g_rowptr[n1 + 1]; sc1 = g_deginv[n1]; }

        // interleaved phase: both nodes issue 4-row batches together (MLP=8)
        while (j0 + 4 <= e0 && j1 + 4 <= e1) {
            uint2 v0[4], v1[4];
#pragma unroll
            for (int k = 0; k < 4; k++)
                v0[k] = *(const uint2*)(H + (size_t)g_colidx[j0 + k] * DDIM + lane * 4);
#pragma unroll
            for (int k = 0; k < 4; k++)
                v1[k] = *(const uint2*)(H + (size_t)g_colidx[j1 + k] * DDIM + lane * 4);
#pragma unroll
            for (int k = 0; k < 4; k++) {
                float2 p0 = __half22float2(*(__half2*)&v0[k].x);
                float2 p1 = __half22float2(*(__half2*)&v0[k].y);
                float4* a = (k & 1) ? &a01 : &a00;
                a->x += p0.x; a->y += p0.y; a->z += p1.x; a->w += p1.y;
                float2 q0 = __half22float2(*(__half2*)&v1[k].x);
                float2 q1 = __half22float2(*(__half2*)&v1[k].y);
                float4* b = (k & 1) ? &a11 : &a10;
                b->x += q0.x; b->y += q0.y; b->z += q1.x; b->w += q1.y;
            }
            j0 += 4; j1 += 4;
        }
        // node 0 remainder
        for (; j0 + 4 <= e0; j0 += 4) {
            uint2 v0[4];
#pragma unroll
            for (int k = 0; k < 4; k++)
                v0[k] = *(const uint2*)(H + (size_t)g_colidx[j0 + k] * DDIM + lane * 4);
#pragma unroll
            for (int k = 0; k < 4; k++) {
                float2 p0 = __half22float2(*(__half2*)&v0[k].x);
                float2 p1 = __half22float2(*(__half2*)&v0[k].y);
                float4* a = (k & 1) ? &a01 : &a00;
                a->x += p0.x; a->y += p0.y; a->z += p1.x; a->w += p1.y;
            }
        }
        for (; j0 < e0; j0++) {
            uint2 v = *(const uint2*)(H + (size_t)g_colidx[j0] * DDIM + lane * 4);
            float2 p0 = __half22float2(*(__half2*)&v.x);
            float2 p1 = __half22float2(*(__half2*)&v.y);
            a00.x += p0.x; a00.y += p0.y; a00.z += p1.x; a00.w += p1.y;
        }
        // node 1 remainder
        for (; j1 + 4 <= e1; j1 += 4) {
            uint2 v1[4];
#pragma unroll
            for (int k = 0; k < 4; k++)
                v1[k] = *(const uint2*)(H + (size_t)g_colidx[j1 + k] * DDIM + lane * 4);
#pragma unroll
            for (int k = 0; k < 4; k++) {
                float2 q0 = __half22float2(*(__half2*)&v1[k].x);
                float2 q1 = __half22float2(*(__half2*)&v1[k].y);
                float4* b = (k & 1) ? &a11 : &a10;
                b->x += q0.x; b->y += q0.y; b->z += q1.x; b->w += q1.y;
            }
        }
        for (; j1 < e1; j1++) {
            uint2 v = *(const uint2*)(H + (size_t)g_colidx[j1] * DDIM + lane * 4);
            float2 q0 = __half22float2(*(__half2*)&v.x);
            float2 q1 = __half22float2(*(__half2*)&v.y);
            a10.x += q0.x; a10.y += q0.y; a10.z += q1.x; a10.w += q1.y;
        }

        uint2 st0, st1;
        st0.x = cvt2((a00.x + a01.x) * sc0, (a00.y + a01.y) * sc0);
        st0.y = cvt2((a00.z + a01.z) * sc0, (a00.w + a01.w) * sc0);
        st1.x = cvt2((a10.x + a11.x) * sc1, (a10.y + a11.y) * sc1);
        st1.y = cvt2((a10.z + a11.z) * sc1, (a10.w + a11.w) * sc1);
        *(uint2*)&smA[lr0 * AWW + (lane >> 2) * 8 + (lane & 3) * 2] = st0;
        *(uint2*)&smA[lr1 * AWW + (lane >> 2) * 8 + (lane & 3) * 2] = st1;
    }
    __syncthreads();

    const unsigned* ar = smA + (rowgrp * 32 + g) * AWW + tig;
    float acc[4][2][4];
#pragma unroll
    for (int t = 0; t < 4; t++)
#pragma unroll
        for (int s = 0; s < 2; s++)
#pragma unroll
            for (int i = 0; i < 4; i++) acc[t][s][i] = 0.f;

#pragma unroll
    for (int ksf = 0; ksf < KCH; ksf++) {
        uint2 bb[4];
#pragma unroll
        for (int t = 0; t < 4; t++)
            bb[t] = Bf[bbase0 + (t * KCH + ksf) * 32];
        unsigned aH[2][4];
        aH[0][0] = ar[ksf * 8];
        aH[0][1] = ar[8 * AWW + ksf * 8];
        aH[0][2] = ar[ksf * 8 + 4];
        aH[0][3] = ar[8 * AWW + ksf * 8 + 4];
        aH[1][0] = ar[16 * AWW + ksf * 8];
        aH[1][1] = ar[24 * AWW + ksf * 8];
        aH[1][2] = ar[16 * AWW + ksf * 8 + 4];
        aH[1][3] = ar[24 * AWW + ksf * 8 + 4];
#pragma unroll
        for (int t = 0; t < 4; t++) {
            mma_f16(acc[t][0], aH[0], bb[t].x, bb[t].y);
            mma_f16(acc[t][1], aH[1], bb[t].x, bb[t].y);
        }
    }

    if (EPI == 1) {
        __half* out = (__half*)outv;
#pragma unroll
        for (int t = 0; t < 4; t++) {
            const int c = colq * 32 + t * 8 + tig * 2;
            float2 bb = *(const float2*)(bias + c);
#pragma unroll
            for (int s2 = 0; s2 < 4; s2++) {
                if (!pp[s2]) continue;
                float ax, ay;
                if ((s2 & 1) == 0) { ax = acc[t][s2>>1][0]; ay = acc[t][s2>>1][1]; }
                else               { ax = acc[t][s2>>1][2]; ay = acc[t][s2>>1][3]; }
                float vx = fmaxf(ax + bb.x, 0.f);
                float vy = fmaxf(ay + bb.y, 0.f);
                float2 id;
                if (IDIN == 0) {
                    id = *(const float2*)(identityf + (size_t)rr[s2] * DDIM + c);
                } else {
                    int lr2 = rowgrp * 32 + g + s2 * 8;
                    unsigned iv = smA[lr2 * AWW + 64 + (c >> 4) * 8 + ((c & 15) >> 1)];
                    id = __half22float2(*(__half2*)&iv);
                }
                *(unsigned*)(out + (size_t)rr[s2] * DDIM + c) = cvt2(vx + id.x, vy + id.y);
            }
        }
    } else {
        float* out = (float*)outv;
        float ss[4] = {0.f, 0.f, 0.f, 0.f};
#pragma unroll
        for (int t = 0; t < 4; t++) {
            const int c = colq * 32 + t * 8 + tig * 2;
            float2 bb = *(const float2*)(bias + c);
#pragma unroll
            for (int s = 0; s < 2; s++) {
                acc[t][s][0] += bb.x; acc[t][s][1] += bb.y;
                acc[t][s][2] += bb.x; acc[t][s][3] += bb.y;
                ss[2*s]   += acc[t][s][0] * acc[t][s][0] + acc[t][s][1] * acc[t][s][1];
                ss[2*s+1] += acc[t][s][2] * acc[t][s][2] + acc[t][s][3] * acc[t][s][3];
            }
        }
#pragma unroll
        for (int i = 0; i < 4; i++) {
            ss[i] += __shfl_xor_sync(0xffffffffu, ss[i], 1);
            ss[i] += __shfl_xor_sync(0xffffffffu, ss[i], 2);
        }
        __syncthreads();
        if (tig == 0) {
#pragma unroll
            for (int i = 0; i < 4; i++) s_red[colq][rowgrp][i * 8 + g] = ss[i];
        }
        __syncthreads();
        float inv[4];
#pragma unroll
        for (int i = 0; i < 4; i++) {
            float tot = s_red[0][rowgrp][i * 8 + g] + s_red[1][rowgrp][i * 8 + g]
                      + s_red[2][rowgrp][i * 8 + g] + s_red[3][rowgrp][i * 8 + g];
            inv[i] = 1.f / fmaxf(sqrtf(tot), 1e-12f);
        }
#pragma unroll
        for (int t = 0; t < 4; t++) {
            const int c = colq * 32 + t * 8 + tig * 2;
#pragma unroll
            for (int s = 0; s < 2; s++) {
                if (pp[2*s])
                    *(float2*)(out + (size_t)rr[2*s] * DDIM + c) =
                        make_float2(acc[t][s][0] * inv[2*s], acc[t][s][1] * inv[2*s]);
                if (pp[2*s+1])
                    *(float2*)(out + (size_t)rr[2*s+1] * DDIM + c) =
                        make_float2(acc[t][s][2] * inv[2*s+1], acc[t][s][3] * inv[2*s+1]);
            }
        }
    }
}

#define SM1 (128 * 68 * 4)    // KH=1 A panel (34.8 KB)
#define SM2 (128 * 132 * 4)   // KH=2 A panel (67.6 KB)

// ---------------- launch ----------------
extern "C" void kernel_launch(void* const* d_in, const int* in_sizes, int n_in,
                              void* d_out, int out_size) {
    const float* x      = (const float*)d_in[0];
    const void*  ei     = d_in[1];
    const float* W_proj = (const float*)d_in[2];
    const float* W1_l   = (const float*)d_in[3];
    const float* b1     = (const float*)d_in[4];
    const float* W1_r   = (const float*)d_in[5];
    const float* W2_l   = (const float*)d_in[6];
    const float* b2     = (const float*)d_in[7];
    const float* W2_r   = (const float*)d_in[8];
    const float* W3_l   = (const float*)d_in[9];
    const float* b3     = (const float*)d_in[10];
    const float* W3_r   = (const float*)d_in[11];
    float* out = (float*)d_out;

    __half *bufA, *bufB;
    unsigned *Wp, *Wb;
    cudaGetSymbolAddress((void**)&bufA, g_bufA);
    cudaGetSymbolAddress((void**)&bufB, g_bufB);
    cudaGetSymbolAddress((void**)&Wp,   g_Wp);
    cudaGetSymbolAddress((void**)&Wb,   g_Wb);
    unsigned* Wb0 = Wb;
    unsigned* Wb1 = Wb + DDIM * 16 * 8;
    unsigned* Wb2 = Wb + 2 * DDIM * 16 * 8;

    static int attr_done = 0;
    if (!attr_done) {
        cudaFuncSetAttribute(k_gemm_proj,     cudaFuncAttributeMaxDynamicSharedMemorySize, SM1);
        cudaFuncSetAttribute(k_gemm_agg<1,0>, cudaFuncAttributeMaxDynamicSharedMemorySize, SM2);
        cudaFuncSetAttribute(k_gemm_agg<1,2>, cudaFuncAttributeMaxDynamicSharedMemorySize, SM2);
        cudaFuncSetAttribute(k_gemm_agg<2,0>, cudaFuncAttributeMaxDynamicSharedMemorySize, SM2);
        attr_done = 1;
    }

    // 1: fused weight conversion (R12 layout)
    ConvArgs ca;
    ca.src[0] = W_proj; ca.dst[0] = Wp;  ca.koff[0] = 0;   ca.kfull[0] = 128;
    ca.src[1] = W1_l;   ca.dst[1] = Wb0; ca.koff[1] = 0;   ca.kfull[1] = 256;
    ca.src[2] = W1_r;   ca.dst[2] = Wb0; ca.koff[2] = 128; ca.kfull[2] = 256;
    ca.src[3] = W2_l;   ca.dst[3] = Wb1; ca.koff[3] = 0;   ca.kfull[3] = 256;
    ca.src[4] = W2_r;   ca.dst[4] = Wb1; ca.koff[4] = 128; ca.kfull[4] = 256;
    ca.src[5] = W3_l;   ca.dst[5] = Wb2; ca.koff[5] = 0;   ca.kfull[5] = 256;
    ca.src[6] = W3_r;   ca.dst[6] = Wb2; ca.koff[6] = 128; ca.kfull[6] = 256;
    k_convert_all<<<dim3(64, 7), 256>>>(ca);

    // 2: init deg + prefix dtype detect
    k_init<<<SBLK, 256>>>((const unsigned*)ei);

    // 3: degree histogram
    k_hist<<<(EE + 255) / 256, 256>>>(ei);

    // 4: proj GEMM (profiled slot): h0 = x @ Wproj^T
    k_gemm_proj<<<NBLK, 512, SM1>>>(x, Wp, bufA);

    // 5-7: parallel scan
    k_scan1<<<SBLK, 256>>>();
    k_scan2<<<1, 512>>>();
    k_scan3<<<SBLK, 256>>>();

    // 8: CSR fill
    k_fill<<<(EE + 255) / 256, 256>>>(ei);

    // layer 1: h1 = relu([mean(h0)|h0] @ W1 + b1) + x
    k_gemm_agg<1, 0><<<NBLK, 512, SM2>>>(bufA, Wb0, b1, x, bufB);

    // layer 2: h2 = relu([mean(h1)|h1] @ W2 + b2) + h1
    k_gemm_agg<1, 2><<<NBLK, 512, SM2>>>(bufB, Wb1, b2, nullptr, bufA);

    // layer 3: out = normalize([mean(h2)|h2] @ W3 + b3)
    k_gemm_agg<2, 0><<<NBLK, 512, SM2>>>(bufA, Wb2, b3, nullptr, out);
}

// round 17
// speedup vs baseline: 1.2066x; 1.0104x over previous
#include <cuda_runtime.h>
#include <cuda_fp16.h>
#include <stdint.h>
#include <math.h>

#define NN   100000
#define EE   800000
#define DDIM 128
#define NBLK 782      // 782*128 = 100096 rows
#define SBLK 391      // scan blocks: 391*256 >= NN

// ---------------- scratch (device globals; no runtime alloc) ----------------
__device__ __align__(256) __half g_bufA[(size_t)NBLK * 128 * DDIM];
__device__ __align__(256) __half g_bufB[(size_t)NBLK * 128 * DDIM];
__device__ int   g_deg[NN];
__device__ int   g_rowptr[NN + 1];
__device__ int   g_cursor[NN];
__device__ float g_deginv[NN];
__device__ int   g_colidx[EE];
__device__ int   g_part[512];
__device__ int   g_is64;
// fragment-packed fp16 weights (hi only), warp-contiguous (R12 layout):
// u32 idx = (((nb*KCH + ksf)*8 + g)*4 + tig)*2 + half   (n = nb*8+g)
__device__ __align__(16) unsigned g_Wp[DDIM * 8 * 8];         // proj  KCH=8
__device__ __align__(16) unsigned g_Wb[3][DDIM * 16 * 8];     // layers KCH=16

// ---------------- init + prefix dtype detect ----------------
__global__ void k_init(const unsigned* __restrict__ w) {
    int i = blockIdx.x * blockDim.x + threadIdx.x;
    if (i < NN) g_deg[i] = 0;
    if (blockIdx.x == 0) {
        if (threadIdx.x == 0) g_is64 = 1;
        __syncthreads();
        unsigned acc = 0;
#pragma unroll
        for (int k = 0; k < 16; k++)
            acc |= w[2 * (threadIdx.x + k * 256) + 1];
        if (acc != 0) g_is64 = 0;
    }
}
__device__ __forceinline__ int load_idx(const void* ei, int pos, int is64) {
    if (is64) return (int)((const long long*)ei)[pos];
    return ((const int*)ei)[pos];
}
__global__ void k_hist(const void* __restrict__ ei) {
    int e = blockIdx.x * blockDim.x + threadIdx.x;
    if (e < EE) {
        int d = load_idx(ei, EE + e, g_is64);
        if ((unsigned)d < NN) atomicAdd(&g_deg[d], 1);
    }
}

// ---------------- parallel 3-phase exclusive scan ----------------
__global__ void k_scan1() {
    __shared__ int sh[256];
    int t = threadIdx.x;
    int i = blockIdx.x * 256 + t;
    sh[t] = (i < NN) ? g_deg[i] : 0;
    __syncthreads();
#pragma unroll
    for (int off = 128; off > 0; off >>= 1) {
        if (t < off) sh[t] += sh[t + off];
        __syncthreads();
    }
    if (t == 0) g_part[blockIdx.x] = sh[0];
}
__global__ void k_scan2() {
    __shared__ int sh[512];
    int t = threadIdx.x;
    int v = (t < SBLK) ? g_part[t] : 0;
    sh[t] = v;
    __syncthreads();
#pragma unroll
    for (int off = 1; off < 512; off <<= 1) {
        int u = (t >= off) ? sh[t - off] : 0;
        __syncthreads();
        sh[t] += u;
        __syncthreads();
    }
    if (t < SBLK) g_part[t] = sh[t] - v;
    if (t == SBLK - 1) g_rowptr[NN] = sh[t];
}
__global__ void k_scan3() {
    __shared__ int sh[256];
    int t = threadIdx.x;
    int i = blockIdx.x * 256 + t;
    int d = (i < NN) ? g_deg[i] : 0;
    sh[t] = d;
    __syncthreads();
#pragma unroll
    for (int off = 1; off < 256; off <<= 1) {
        int u = (t >= off) ? sh[t - off] : 0;
        __syncthreads();
        sh[t] += u;
        __syncthreads();
    }
    if (i < NN) {
        int excl = sh[t] - d + g_part[blockIdx.x];
        g_rowptr[i] = excl;
        g_cursor[i] = excl;
        g_deginv[i] = (d > 0) ? 1.0f / (float)d : 0.0f;
    }
}
__global__ void k_fill(const void* __restrict__ ei) {
    int e = blockIdx.x * blockDim.x + threadIdx.x;
    if (e < EE) {
        int is64 = g_is64;
        int s = load_idx(ei, e, is64);
        int d = load_idx(ei, EE + e, is64);
        if ((unsigned)d < NN && (unsigned)s < NN) {
            int p = atomicAdd(&g_cursor[d], 1);
            g_colidx[p] = s;
        }
    }
}

// ---------------- weight conversion: fp32 -> fragment-packed fp16 (R12 layout) ----------------
struct ConvArgs {
    const float*  src[7];
    unsigned*     dst[7];
    int           koff[7];
    int           kfull[7];
};
__global__ void k_convert_all(ConvArgs a) {
    int m = blockIdx.y;
    int idx = blockIdx.x * blockDim.x + threadIdx.x;
    if (idx >= DDIM * DDIM) return;
    int n = idx >> 7, k = idx & 127;
    __half h = __float2half_rn(a.src[m][idx]);
    int kg   = a.koff[m] + k;
    int ksf  = kg >> 4;
    int kpos = kg & 15;
    int tig  = (kpos >> 1) & 3;
    int hf   = kpos >> 3;
    int b    = kpos & 1;
    unsigned u32i = ((((unsigned)((n >> 3) * (a.kfull[m] >> 4) + ksf) * 8 + (n & 7)) * 4 + tig) * 2 + hf);
    ((__half*)a.dst[m])[u32i * 2 + b] = h;
}

// ---------------- common GEMM pieces ----------------
__device__ __forceinline__ unsigned cvt2(float x, float y) {
    __half2 t = __floats2half2_rn(x, y);
    return *reinterpret_cast<unsigned*>(&t);
}
__device__ __forceinline__ void mma_f16(float (&c)[4], const unsigned (&a)[4],
                                        unsigned b0, unsigned b1) {
    asm volatile(
        "mma.sync.aligned.m16n8k16.row.col.f32.f16.f16.f32 "
        "{%0,%1,%2,%3}, {%4,%5,%6,%7}, {%8,%9}, {%0,%1,%2,%3};\n"
        : "+f"(c[0]), "+f"(c[1]), "+f"(c[2]), "+f"(c[3])
        : "r"(a[0]), "r"(a[1]), "r"(a[2]), "r"(a[3]), "r"(b0), "r"(b1));
}
// A smem (R12): 128 rows x (KH*128) k fp16, word stride AWW = KH*64 + 4
// word(row, k) = row*AWW + (k>>4)*8 + ((k&15)>>1)

// ---------------- proj GEMM (KH=1, fp32 A in, fp16 out) — R12 verbatim ----------------
__global__ void __launch_bounds__(512, 2) k_gemm_proj(
    const float* __restrict__ A0, const unsigned* __restrict__ Bfrag,
    __half* __restrict__ out)
{
    constexpr int KCH = 8;
    constexpr int AWW = 68;
    extern __shared__ unsigned smA[];
    const int tid = threadIdx.x;
    const int w = tid >> 5;
    const int lane = tid & 31;
    const int g = lane >> 2;
    const int tig = lane & 3;
    const int rowgrp = w & 3;
    const int colq = w >> 2;
    const int rowbase = blockIdx.x * 128 + rowgrp * 32;
    int rr[4] = { rowbase + g, rowbase + g + 8, rowbase + g + 16, rowbase + g + 24 };
    bool pp[4];
#pragma unroll
    for (int i = 0; i < 4; i++) pp[i] = rr[i] < NN;

    const uint2* Bf = (const uint2*)Bfrag;
    const int bbase0 = (colq * 4 * KCH) * 32 + g * 4 + tig;

#pragma unroll
    for (int it = 0; it < 8; it++) {
        int idx = it * 512 + tid;
        int row = idx >> 5, l = idx & 31;
        int grow = blockIdx.x * 128 + row;
        float4 fv = make_float4(0.f, 0.f, 0.f, 0.f);
        if (grow < NN) fv = *(const float4*)(A0 + (size_t)grow * DDIM + l * 4);
        uint2 st;
        st.x = cvt2(fv.x, fv.y);
        st.y = cvt2(fv.z, fv.w);
        *(uint2*)&smA[row * AWW + (l >> 2) * 8 + (l & 3) * 2] = st;
    }
    __syncthreads();

    const unsigned* ar = smA + (rowgrp * 32 + g) * AWW + tig;
    float acc[4][2][4];
#pragma unroll
    for (int t = 0; t < 4; t++)
#pragma unroll
        for (int s = 0; s < 2; s++)
#pragma unroll
            for (int i = 0; i < 4; i++) acc[t][s][i] = 0.f;

#pragma unroll
    for (int ksf = 0; ksf < KCH; ksf++) {
        uint2 bb[4];
#pragma unroll
        for (int t = 0; t < 4; t++)
            bb[t] = Bf[bbase0 + (t * KCH + ksf) * 32];
        unsigned aH[2][4];
        aH[0][0] = ar[ksf * 8];
        aH[0][1] = ar[8 * AWW + ksf * 8];
        aH[0][2] = ar[ksf * 8 + 4];
        aH[0][3] = ar[8 * AWW + ksf * 8 + 4];
        aH[1][0] = ar[16 * AWW + ksf * 8];
        aH[1][1] = ar[24 * AWW + ksf * 8];
        aH[1][2] = ar[16 * AWW + ksf * 8 + 4];
        aH[1][3] = ar[24 * AWW + ksf * 8 + 4];
#pragma unroll
        for (int t = 0; t < 4; t++) {
            mma_f16(acc[t][0], aH[0], bb[t].x, bb[t].y);
            mma_f16(acc[t][1], aH[1], bb[t].x, bb[t].y);
        }
    }
#pragma unroll
    for (int t = 0; t < 4; t++) {
        const int c = colq * 32 + t * 8 + tig * 2;
#pragma unroll
        for (int s = 0; s < 2; s++) {
            if (pp[2*s])
                *(unsigned*)(out + (size_t)rr[2*s] * DDIM + c) = cvt2(acc[t][s][0], acc[t][s][1]);
            if (pp[2*s+1])
                *(unsigned*)(out + (size_t)rr[2*s+1] * DDIM + c) = cvt2(acc[t][s][2], acc[t][s][3]);
        }
    }
}

// ---------------- fused layer GEMM (R16: R12 + dual-node interleaved gather) ----------------
// EPI: 1 = relu(acc+bias)+identity, 2 = bias + L2-norm -> fp32
// IDIN: 0 = identity fp32 global, 2 = identity = h (smem A1 panel)
template<int EPI, int IDIN>
__global__ void __launch_bounds__(512, 2) k_gemm_agg(
    const __half* __restrict__ H, const unsigned* __restrict__ Bfrag,
    const float* __restrict__ bias, const float* __restrict__ identityf,
    void* __restrict__ outv)
{
    constexpr int KCH = 16;
    constexpr int AWW = 132;
    extern __shared__ unsigned smA[];
    __shared__ float s_red[4][4][32];

    const int tid = threadIdx.x;
    const int w = tid >> 5;
    const int lane = tid & 31;
    const int g = lane >> 2;
    const int tig = lane & 3;
    const int rowgrp = w & 3;
    const int colq = w >> 2;
    const int rowbase = blockIdx.x * 128 + rowgrp * 32;
    int rr[4] = { rowbase + g, rowbase + g + 8, rowbase + g + 16, rowbase + g + 24 };
    bool pp[4];
#pragma unroll
    for (int i = 0; i < 4; i++) pp[i] = rr[i] < NN;

    const uint2* Bf = (const uint2*)Bfrag;
    const int bbase0 = (colq * 4 * KCH) * 32 + g * 4 + tig;

    // ---- A1: own h rows (k 128..255), contiguous uint4 copy ----
#pragma unroll
    for (int it = 0; it < 4; it++) {
        int idx = it * 512 + tid;
        int row = idx >> 4, l = idx & 15;
        int grow = blockIdx.x * 128 + row;
        uint4 v = make_uint4(0u, 0u, 0u, 0u);
        if (grow < NN) v = *(const uint4*)(H + (size_t)grow * DDIM + l * 8);
        *(uint4*)&smA[row * AWW + 64 + (l >> 1) * 8 + (l & 1) * 4] = v;
    }

    // ---- A0: gather-mean, warp w handles 8 nodes as 4 interleaved pairs ----
#pragma unroll 1
    for (int pi = 0; pi < 4; pi++) {
        int lr0 = w * 8 + pi * 2;
        int lr1 = lr0 + 1;
        int n0 = blockIdx.x * 128 + lr0;
        int n1 = n0 + 1;
        float4 a00 = make_float4(0.f,0.f,0.f,0.f), a01 = make_float4(0.f,0.f,0.f,0.f);
        float4 a10 = make_float4(0.f,0.f,0.f,0.f), a11 = make_float4(0.f,0.f,0.f,0.f);
        int j0 = 0, e0 = 0, j1 = 0, e1 = 0;
        float sc0 = 0.f, sc1 = 0.f;
        if (n0 < NN) { j0 = g_rowptr[n0]; e0 = g_rowptr[n0 + 1]; sc0 = g_deginv[n0]; }
        if (n1 < NN) { j1 = g_rowptr[n1]; e1 = g_rowptr[n1 + 1]; sc1 = g_deginv[n1]; }

        while (j0 + 4 <= e0 && j1 + 4 <= e1) {
            uint2 v0[4], v1[4];
#pragma unroll
            for (int k = 0; k < 4; k++)
                v0[k] = *(const uint2*)(H + (size_t)g_colidx[j0 + k] * DDIM + lane * 4);
#pragma unroll
            for (int k = 0; k < 4; k++)
                v1[k] = *(const uint2*)(H + (size_t)g_colidx[j1 + k] * DDIM + lane * 4);
#pragma unroll
            for (int k = 0; k < 4; k++) {
                float2 p0 = __half22float2(*(__half2*)&v0[k].x);
                float2 p1 = __half22float2(*(__half2*)&v0[k].y);
                float4* a = (k & 1) ? &a01 : &a00;
                a->x += p0.x; a->y += p0.y; a->z += p1.x; a->w += p1.y;
                float2 q0 = __half22float2(*(__half2*)&v1[k].x);
                float2 q1 = __half22float2(*(__half2*)&v1[k].y);
                float4* b = (k & 1) ? &a11 : &a10;
                b->x += q0.x; b->y += q0.y; b->z += q1.x; b->w += q1.y;
            }
            j0 += 4; j1 += 4;
        }
        for (; j0 + 4 <= e0; j0 += 4) {
            uint2 v0[4];
#pragma unroll
            for (int k = 0; k < 4; k++)
                v0[k] = *(const uint2*)(H + (size_t)g_colidx[j0 + k] * DDIM + lane * 4);
#pragma unroll
            for (int k = 0; k < 4; k++) {
                float2 p0 = __half22float2(*(__half2*)&v0[k].x);
                float2 p1 = __half22float2(*(__half2*)&v0[k].y);
                float4* a = (k & 1) ? &a01 : &a00;
                a->x += p0.x; a->y += p0.y; a->z += p1.x; a->w += p1.y;
            }
        }
        for (; j0 < e0; j0++) {
            uint2 v = *(const uint2*)(H + (size_t)g_colidx[j0] * DDIM + lane * 4);
            float2 p0 = __half22float2(*(__half2*)&v.x);
            float2 p1 = __half22float2(*(__half2*)&v.y);
            a00.x += p0.x; a00.y += p0.y; a00.z += p1.x; a00.w += p1.y;
        }
        for (; j1 + 4 <= e1; j1 += 4) {
            uint2 v1[4];
#pragma unroll
            for (int k = 0; k < 4; k++)
                v1[k] = *(const uint2*)(H + (size_t)g_colidx[j1 + k] * DDIM + lane * 4);
#pragma unroll
            for (int k = 0; k < 4; k++) {
                float2 q0 = __half22float2(*(__half2*)&v1[k].x);
                float2 q1 = __half22float2(*(__half2*)&v1[k].y);
                float4* b = (k & 1) ? &a11 : &a10;
                b->x += q0.x; b->y += q0.y; b->z += q1.x; b->w += q1.y;
            }
        }
        for (; j1 < e1; j1++) {
            uint2 v = *(const uint2*)(H + (size_t)g_colidx[j1] * DDIM + lane * 4);
            float2 q0 = __half22float2(*(__half2*)&v.x);
            float2 q1 = __half22float2(*(__half2*)&v.y);
            a10.x += q0.x; a10.y += q0.y; a10.z += q1.x; a10.w += q1.y;
        }

        uint2 st0, st1;
        st0.x = cvt2((a00.x + a01.x) * sc0, (a00.y + a01.y) * sc0);
        st0.y = cvt2((a00.z + a01.z) * sc0, (a00.w + a01.w) * sc0);
        st1.x = cvt2((a10.x + a11.x) * sc1, (a10.y + a11.y) * sc1);
        st1.y = cvt2((a10.z + a11.z) * sc1, (a10.w + a11.w) * sc1);
        *(uint2*)&smA[lr0 * AWW + (lane >> 2) * 8 + (lane & 3) * 2] = st0;
        *(uint2*)&smA[lr1 * AWW + (lane >> 2) * 8 + (lane & 3) * 2] = st1;
    }
    __syncthreads();

    const unsigned* ar = smA + (rowgrp * 32 + g) * AWW + tig;
    float acc[4][2][4];
#pragma unroll
    for (int t = 0; t < 4; t++)
#pragma unroll
        for (int s = 0; s < 2; s++)
#pragma unroll
            for (int i = 0; i < 4; i++) acc[t][s][i] = 0.f;

#pragma unroll
    for (int ksf = 0; ksf < KCH; ksf++) {
        uint2 bb[4];
#pragma unroll
        for (int t = 0; t < 4; t++)
            bb[t] = Bf[bbase0 + (t * KCH + ksf) * 32];
        unsigned aH[2][4];
        aH[0][0] = ar[ksf * 8];
        aH[0][1] = ar[8 * AWW + ksf * 8];
        aH[0][2] = ar[ksf * 8 + 4];
        aH[0][3] = ar[8 * AWW + ksf * 8 + 4];
        aH[1][0] = ar[16 * AWW + ksf * 8];
        aH[1][1] = ar[24 * AWW + ksf * 8];
        aH[1][2] = ar[16 * AWW + ksf * 8 + 4];
        aH[1][3] = ar[24 * AWW + ksf * 8 + 4];
#pragma unroll
        for (int t = 0; t < 4; t++) {
            mma_f16(acc[t][0], aH[0], bb[t].x, bb[t].y);
            mma_f16(acc[t][1], aH[1], bb[t].x, bb[t].y);
        }
    }

    if (EPI == 1) {
        __half* out = (__half*)outv;
#pragma unroll
        for (int t = 0; t < 4; t++) {
            const int c = colq * 32 + t * 8 + tig * 2;
            float2 bb = *(const float2*)(bias + c);
#pragma unroll
            for (int s2 = 0; s2 < 4; s2++) {
                if (!pp[s2]) continue;
                float ax, ay;
                if ((s2 & 1) == 0) { ax = acc[t][s2>>1][0]; ay = acc[t][s2>>1][1]; }
                else               { ax = acc[t][s2>>1][2]; ay = acc[t][s2>>1][3]; }
                float vx = fmaxf(ax + bb.x, 0.f);
                float vy = fmaxf(ay + bb.y, 0.f);
                float2 id;
                if (IDIN == 0) {
                    id = *(const float2*)(identityf + (size_t)rr[s2] * DDIM + c);
                } else {
                    int lr2 = rowgrp * 32 + g + s2 * 8;
                    unsigned iv = smA[lr2 * AWW + 64 + (c >> 4) * 8 + ((c & 15) >> 1)];
                    id = __half22float2(*(__half2*)&iv);
                }
                *(unsigned*)(out + (size_t)rr[s2] * DDIM + c) = cvt2(vx + id.x, vy + id.y);
            }
        }
    } else {
        float* out = (float*)outv;
        float ss[4] = {0.f, 0.f, 0.f, 0.f};
#pragma unroll
        for (int t = 0; t < 4; t++) {
            const int c = colq * 32 + t * 8 + tig * 2;
            float2 bb = *(const float2*)(bias + c);
#pragma unroll
            for (int s = 0; s < 2; s++) {
                acc[t][s][0] += bb.x; acc[t][s][1] += bb.y;
                acc[t][s][2] += bb.x; acc[t][s][3] += bb.y;
                ss[2*s]   += acc[t][s][0] * acc[t][s][0] + acc[t][s][1] * acc[t][s][1];
                ss[2*s+1] += acc[t][s][2] * acc[t][s][2] + acc[t][s][3] * acc[t][s][3];
            }
        }
#pragma unroll
        for (int i = 0; i < 4; i++) {
            ss[i] += __shfl_xor_sync(0xffffffffu, ss[i], 1);
            ss[i] += __shfl_xor_sync(0xffffffffu, ss[i], 2);
        }
        __syncthreads();
        if (tig == 0) {
#pragma unroll
            for (int i = 0; i < 4; i++) s_red[colq][rowgrp][i * 8 + g] = ss[i];
        }
        __syncthreads();
        float inv[4];
#pragma unroll
        for (int i = 0; i < 4; i++) {
            float tot = s_red[0][rowgrp][i * 8 + g] + s_red[1][rowgrp][i * 8 + g]
                      + s_red[2][rowgrp][i * 8 + g] + s_red[3][rowgrp][i * 8 + g];
            inv[i] = 1.f / fmaxf(sqrtf(tot), 1e-12f);
        }
#pragma unroll
        for (int t = 0; t < 4; t++) {
            const int c = colq * 32 + t * 8 + tig * 2;
#pragma unroll
            for (int s = 0; s < 2; s++) {
                if (pp[2*s])
                    *(float2*)(out + (size_t)rr[2*s] * DDIM + c) =
                        make_float2(acc[t][s][0] * inv[2*s], acc[t][s][1] * inv[2*s]);
                if (pp[2*s+1])
                    *(float2*)(out + (size_t)rr[2*s+1] * DDIM + c) =
                        make_float2(acc[t][s][2] * inv[2*s+1], acc[t][s][3] * inv[2*s+1]);
            }
        }
    }
}

#define SM1 (128 * 68 * 4)    // KH=1 A panel (34.8 KB)
#define SM2 (128 * 132 * 4)   // KH=2 A panel (67.6 KB)

// ---------------- launch ----------------
extern "C" void kernel_launch(void* const* d_in, const int* in_sizes, int n_in,
                              void* d_out, int out_size) {
    const float* x      = (const float*)d_in[0];
    const void*  ei     = d_in[1];
    const float* W_proj = (const float*)d_in[2];
    const float* W1_l   = (const float*)d_in[3];
    const float* b1     = (const float*)d_in[4];
    const float* W1_r   = (const float*)d_in[5];
    const float* W2_l   = (const float*)d_in[6];
    const float* b2     = (const float*)d_in[7];
    const float* W2_r   = (const float*)d_in[8];
    const float* W3_l   = (const float*)d_in[9];
    const float* b3     = (const float*)d_in[10];
    const float* W3_r   = (const float*)d_in[11];
    float* out = (float*)d_out;

    __half *bufA, *bufB;
    unsigned *Wp, *Wb;
    cudaGetSymbolAddress((void**)&bufA, g_bufA);
    cudaGetSymbolAddress((void**)&bufB, g_bufB);
    cudaGetSymbolAddress((void**)&Wp,   g_Wp);
    cudaGetSymbolAddress((void**)&Wb,   g_Wb);
    unsigned* Wb0 = Wb;
    unsigned* Wb1 = Wb + DDIM * 16 * 8;
    unsigned* Wb2 = Wb + 2 * DDIM * 16 * 8;

    // one-time resources (created on the uncaptured correctness run)
    static cudaStream_t s2 = nullptr;
    static cudaEvent_t evA = nullptr, evB = nullptr;
    if (!s2) {
        cudaStreamCreateWithFlags(&s2, cudaStreamNonBlocking);
        cudaEventCreateWithFlags(&evA, cudaEventDisableTiming);
        cudaEventCreateWithFlags(&evB, cudaEventDisableTiming);
        cudaFuncSetAttribute(k_gemm_proj,     cudaFuncAttributeMaxDynamicSharedMemorySize, SM1);
        cudaFuncSetAttribute(k_gemm_agg<1,0>, cudaFuncAttributeMaxDynamicSharedMemorySize, SM2);
        cudaFuncSetAttribute(k_gemm_agg<1,2>, cudaFuncAttributeMaxDynamicSharedMemorySize, SM2);
        cudaFuncSetAttribute(k_gemm_agg<2,0>, cudaFuncAttributeMaxDynamicSharedMemorySize, SM2);
    }

    // fork: CSR chain on s2; converts + proj GEMM on main stream
    cudaEventRecord(evA, 0);
    cudaStreamWaitEvent(s2, evA, 0);

    k_init<<<SBLK, 256, 0, s2>>>((const unsigned*)ei);
    k_hist<<<(EE + 255) / 256, 256, 0, s2>>>(ei);
    k_scan1<<<SBLK, 256, 0, s2>>>();
    k_scan2<<<1, 512, 0, s2>>>();
    k_scan3<<<SBLK, 256, 0, s2>>>();
    k_fill<<<(EE + 255) / 256, 256, 0, s2>>>(ei);
    cudaEventRecord(evB, s2);

    // main stream: weight conversion + proj GEMM (independent of CSR)
    ConvArgs ca;
    ca.src[0] = W_proj; ca.dst[0] = Wp;  ca.koff[0] = 0;   ca.kfull[0] = 128;
    ca.src[1] = W1_l;   ca.dst[1] = Wb0; ca.koff[1] = 0;   ca.kfull[1] = 256;
    ca.src[2] = W1_r;   ca.dst[2] = Wb0; ca.koff[2] = 128; ca.kfull[2] = 256;
    ca.src[3] = W2_l;   ca.dst[3] = Wb1; ca.koff[3] = 0;   ca.kfull[3] = 256;
    ca.src[4] = W2_r;   ca.dst[4] = Wb1; ca.koff[4] = 128; ca.kfull[4] = 256;
    ca.src[5] = W3_l;   ca.dst[5] = Wb2; ca.koff[5] = 0;   ca.kfull[5] = 256;
    ca.src[6] = W3_r;   ca.dst[6] = Wb2; ca.koff[6] = 128; ca.kfull[6] = 256;
    k_convert_all<<<dim3(64, 7), 256>>>(ca);

    k_gemm_proj<<<NBLK, 512, SM1>>>(x, Wp, bufA);

    // join: layers need the CSR
    cudaStreamWaitEvent(0, evB, 0);

    // layer 1: h1 = relu([mean(h0)|h0] @ W1 + b1) + x
    k_gemm_agg<1, 0><<<NBLK, 512, SM2>>>(bufA, Wb0, b1, x, bufB);

    // layer 2: h2 = relu([mean(h1)|h1] @ W2 + b2) + h1
    k_gemm_agg<1, 2><<<NBLK, 512, SM2>>>(bufB, Wb1, b2, nullptr, bufA);

    // layer 3: out = normalize([mean(h2)|h2] @ W3 + b3)
    k_gemm_agg<2, 0><<<NBLK, 512, SM2>>>(bufA, Wb2, b3, nullptr, out);
}